// round 3
// baseline (speedup 1.0000x reference)
#include <cuda_runtime.h>
#include <cstdint>

// ---------------- problem dims ----------------
#define BB 4
#define SS 1024
#define DDIM 1024
#define HH 16
#define HDIM 64
#define DFF 4096
#define MTOT (BB*SS)   // 4096

// ---------------- device scratch (no allocs allowed) ----------------
__device__ float g_h   [MTOT*DDIM];       // LN output (reused for ln1 and ln2)
__device__ float g_qkv [MTOT*3*DDIM];     // fused q|k|v
__device__ float g_ctx [MTOT*DDIM];
__device__ float g_x2  [MTOT*DDIM];
__device__ float g_mid [MTOT*DFF];
__device__ float g_wqkv[DDIM*3*DDIM];     // tf32-rounded wq|wk|wv concat
__device__ float g_wo  [DDIM*DDIM];
__device__ float g_w1  [DDIM*DFF];
__device__ float g_w2  [DFF*DDIM];

// ---------------- helpers ----------------
__device__ __forceinline__ float tf32r(float x) {
    uint32_t u;
    asm("cvt.rna.tf32.f32 %0, %1;" : "=r"(u) : "f"(x));
    return __uint_as_float(u);
}

__device__ __forceinline__ void cp16(uint32_t dst, const void* src) {
    asm volatile("cp.async.cg.shared.global [%0], [%1], 16;" :: "r"(dst), "l"(src));
}
__device__ __forceinline__ void cpcommit() { asm volatile("cp.async.commit_group;"); }
template<int N> __device__ __forceinline__ void cpwait() {
    asm volatile("cp.async.wait_group %0;" :: "n"(N));
}

__device__ __forceinline__ float gelu_tanh(float v) {
    const float c = 0.79788456080286535588f;  // sqrt(2/pi)
    float u = c * (v + 0.044715f * v * v * v);
    return 0.5f * v * (1.f + tanhf(u));
}

// ---------------- weight prep: round to tf32 (unbiased) ----------------
__global__ void round_concat_qkv(const float* __restrict__ wq,
                                 const float* __restrict__ wk,
                                 const float* __restrict__ wv,
                                 float* __restrict__ out) {
    int i = blockIdx.x * blockDim.x + threadIdx.x;   // over DDIM * 3*DDIM
    int k = i / (3 * DDIM);
    int n = i % (3 * DDIM);
    const float* src = (n < DDIM) ? wq : (n < 2 * DDIM) ? wk : wv;
    int nn = n & (DDIM - 1);
    out[i] = tf32r(src[k * DDIM + nn]);
}

__global__ void round_copy(const float* __restrict__ w, float* __restrict__ out) {
    int i = blockIdx.x * blockDim.x + threadIdx.x;
    out[i] = tf32r(w[i]);
}

// ---------------- LayerNorm (row = 1024), output rounded to tf32 ----------------
__global__ void ln_kernel(const float* __restrict__ x,
                          const float* __restrict__ scale,
                          const float* __restrict__ shift,
                          float* __restrict__ out) {
    int row = blockIdx.x;
    int t = threadIdx.x;                 // 256 threads, 4 floats each
    const float4* xr = (const float4*)(x + (size_t)row * DDIM);
    float4 v = xr[t];
    float s  = v.x + v.y + v.z + v.w;
    float s2 = v.x*v.x + v.y*v.y + v.z*v.z + v.w*v.w;
    #pragma unroll
    for (int o = 16; o >= 1; o >>= 1) {
        s  += __shfl_xor_sync(0xffffffffu, s,  o);
        s2 += __shfl_xor_sync(0xffffffffu, s2, o);
    }
    __shared__ float red[2][8];
    __shared__ float bcast[2];
    int wid = t >> 5, lane = t & 31;
    if (lane == 0) { red[0][wid] = s; red[1][wid] = s2; }
    __syncthreads();
    if (t == 0) {
        float S = 0.f, S2 = 0.f;
        #pragma unroll
        for (int i = 0; i < 8; i++) { S += red[0][i]; S2 += red[1][i]; }
        float m = S * (1.f / DDIM);
        float var = S2 * (1.f / DDIM) - m * m;
        bcast[0] = m;
        bcast[1] = rsqrtf(var + 1e-5f);
    }
    __syncthreads();
    float m = bcast[0], inv = bcast[1];
    float4 sc = ((const float4*)scale)[t];
    float4 sh = ((const float4*)shift)[t];
    float4 o;
    o.x = tf32r(sc.x * (v.x - m) * inv + sh.x);
    o.y = tf32r(sc.y * (v.y - m) * inv + sh.y);
    o.z = tf32r(sc.z * (v.z - m) * inv + sh.z);
    o.w = tf32r(sc.w * (v.w - m) * inv + sh.w);
    ((float4*)(out + (size_t)row * DDIM))[t] = o;
}

// ---------------- TF32 mma GEMM: C[M,N] = A[M,K] @ W[K,N] (+epilogue) ----------------
// EPI: 0 = plain store, 1 = +bias[n] +res[m,n], 2 = gelu(acc+bias) rounded to tf32
#define BM 128
#define BN 128
#define BKK 16
#define AST 20    // A smem row stride (floats): bank(lane)=lane -> conflict-free frags
#define BST 132   // B smem row stride

template<int EPI>
__global__ void __launch_bounds__(256, 2) gemm_kernel(
    const float* __restrict__ A, const float* __restrict__ Wt,
    const float* __restrict__ bias, const float* __restrict__ res,
    float* __restrict__ C, int Mdim, int Ndim, int Kdim)
{
    __shared__ float As[2][BM * AST];   // 2*10240 B
    __shared__ float Bs[2][BKK * BST];  // 2*8448 B

    const int tid  = threadIdx.x;
    const int bm0  = blockIdx.y * BM;
    const int bn0  = blockIdx.x * BN;
    const int wid  = tid >> 5, lane = tid & 31;
    const int wm   = wid >> 2;      // 0..1  (M)
    const int wn   = wid & 3;       // 0..3  (N)
    const int g    = lane >> 2;     // groupID 0..7
    const int t4   = lane & 3;      // threadID_in_group

    float acc[4][4][4];
    #pragma unroll
    for (int i = 0; i < 4; i++)
        #pragma unroll
        for (int j = 0; j < 4; j++)
            #pragma unroll
            for (int c = 0; c < 4; c++) acc[i][j][c] = 0.f;

    // global/smem load mapping
    const int arow = tid >> 2, ac4 = tid & 3;           // A: 64 rows x 4 float4
    const int brow = tid >> 5, bc4 = tid & 31;          // B: 8 rows x 32 float4
    const float* AgBase = A  + (size_t)(bm0 + arow) * Kdim + ac4 * 4;
    const float* BgBase = Wt + (size_t)brow * Ndim + bn0 + bc4 * 4;
    const uint32_t AsBase = (uint32_t)__cvta_generic_to_shared(&As[0][arow * AST + ac4 * 4]);
    const uint32_t BsBase = (uint32_t)__cvta_generic_to_shared(&Bs[0][brow * BST + bc4 * 4]);
    const uint32_t AsBufB = BM * AST * 4;
    const uint32_t BsBufB = BKK * BST * 4;

    const int KT = Kdim / BKK;

    // prologue: stage tile 0 into buffer 0
    cp16(AsBase,                 AgBase);
    cp16(AsBase + 64 * AST * 4,  AgBase + (size_t)64 * Kdim);
    cp16(BsBase,                 BgBase);
    cp16(BsBase + 8 * BST * 4,   BgBase + (size_t)8 * Ndim);
    cpcommit();

    for (int kt = 0; kt < KT; kt++) {
        const int cb = kt & 1;
        if (kt + 1 < KT) {
            const int nb = (kt + 1) & 1;
            const float* Ag = AgBase + (kt + 1) * BKK;
            const float* Bg = BgBase + (size_t)(kt + 1) * BKK * Ndim;
            cp16(AsBase + nb * AsBufB,                Ag);
            cp16(AsBase + nb * AsBufB + 64 * AST * 4, Ag + (size_t)64 * Kdim);
            cp16(BsBase + nb * BsBufB,                Bg);
            cp16(BsBase + nb * BsBufB + 8 * BST * 4,  Bg + (size_t)8 * Ndim);
            cpcommit();
            cpwait<1>();
        } else {
            cpwait<0>();
        }
        __syncthreads();

        const uint32_t* Asc = (const uint32_t*)As[cb];
        const uint32_t* Bsc = (const uint32_t*)Bs[cb];
        #pragma unroll
        for (int k0 = 0; k0 < BKK; k0 += 8) {
            uint32_t afr[4][4], bfr[4][2];
            #pragma unroll
            for (int i = 0; i < 4; i++) {
                int ar = wm * 64 + i * 16 + g;
                afr[i][0] = Asc[ar * AST + k0 + t4];
                afr[i][1] = Asc[(ar + 8) * AST + k0 + t4];
                afr[i][2] = Asc[ar * AST + k0 + t4 + 4];
                afr[i][3] = Asc[(ar + 8) * AST + k0 + t4 + 4];
            }
            #pragma unroll
            for (int j = 0; j < 4; j++) {
                int bc = wn * 32 + j * 8 + g;
                bfr[j][0] = Bsc[(k0 + t4) * BST + bc];
                bfr[j][1] = Bsc[(k0 + t4 + 4) * BST + bc];
            }
            #pragma unroll
            for (int i = 0; i < 4; i++)
                #pragma unroll
                for (int j = 0; j < 4; j++) {
                    asm volatile(
                        "mma.sync.aligned.m16n8k8.row.col.f32.tf32.tf32.f32 "
                        "{%0,%1,%2,%3},{%4,%5,%6,%7},{%8,%9},{%0,%1,%2,%3};\n"
                        : "+f"(acc[i][j][0]), "+f"(acc[i][j][1]),
                          "+f"(acc[i][j][2]), "+f"(acc[i][j][3])
                        : "r"(afr[i][0]), "r"(afr[i][1]), "r"(afr[i][2]), "r"(afr[i][3]),
                          "r"(bfr[j][0]), "r"(bfr[j][1]));
                }
        }
        __syncthreads();
    }

    // epilogue
    #pragma unroll
    for (int i = 0; i < 4; i++) {
        #pragma unroll
        for (int j = 0; j < 4; j++) {
            int r0 = bm0 + wm * 64 + i * 16 + g;
            int c0 = bn0 + wn * 32 + j * 8 + t4 * 2;
            #pragma unroll
            for (int cr = 0; cr < 4; cr++) {
                int r = r0 + (cr >> 1) * 8;
                int c = c0 + (cr & 1);
                float v = acc[i][j][cr];
                if (EPI == 1) v = v + bias[c] + res[(size_t)r * Ndim + c];
                if (EPI == 2) v = tf32r(gelu_tanh(v + bias[c]));
                C[(size_t)r * Ndim + c] = v;
            }
        }
    }
}

// ---------------- fused causal flash attention (fp32) ----------------
// grid (S/64, H, B), 128 threads. Thread pair (2q,2q+1): q-row split across
// k-halves (scores) and d-halves (output). qkv layout: [b,s, q|k|v of 1024 each].
__global__ void __launch_bounds__(128) attn_kernel(
    const float* __restrict__ qkv, const int* __restrict__ mask,
    float* __restrict__ ctx)
{
    __shared__ float Ks[64 * 64];
    __shared__ float Vs[64 * 64];

    const int b = blockIdx.z, h = blockIdx.y, q0 = blockIdx.x * 64;
    const int t = threadIdx.x;
    const int qr = t >> 1, half = t & 1;
    const int qg = q0 + qr;

    const float* qrow = qkv + (size_t)(b * SS + qg) * 3 * DDIM + h * HDIM;
    float qreg[64];
    #pragma unroll
    for (int d4 = 0; d4 < 16; d4++) {
        float4 qv = ((const float4*)qrow)[d4];
        qreg[d4*4+0] = qv.x * 0.125f;  // 1/sqrt(64)
        qreg[d4*4+1] = qv.y * 0.125f;
        qreg[d4*4+2] = qv.z * 0.125f;
        qreg[d4*4+3] = qv.w * 0.125f;
    }

    float O[32];
    #pragma unroll
    for (int i = 0; i < 32; i++) O[i] = 0.f;
    float mrow = -1e30f, lrow = 0.f;

    const int ntiles = q0 / 64 + 1;
    for (int kt = 0; kt < ntiles; kt++) {
        __syncthreads();
        {   // cooperative K/V tile load: 64 rows x 16 float4 each
            size_t base = (size_t)(b * SS + kt * 64) * 3 * DDIM + h * HDIM;
            for (int i = t; i < 64 * 16; i += 128) {
                int row = i >> 4, c4 = i & 15;
                ((float4*)Ks)[row * 16 + c4] =
                    *(const float4*)(qkv + base + (size_t)row * 3 * DDIM + DDIM + c4 * 4);
                ((float4*)Vs)[row * 16 + c4] =
                    *(const float4*)(qkv + base + (size_t)row * 3 * DDIM + 2 * DDIM + c4 * 4);
            }
        }
        __syncthreads();

        float p[32];
        float mt = -1e30f;
        #pragma unroll
        for (int j = 0; j < 32; j++) {
            int kk = half * 32 + j;
            int kg = kt * 64 + kk;
            const float4* kr = (const float4*)(Ks + kk * 64);
            float s = 0.f;
            #pragma unroll
            for (int d4 = 0; d4 < 16; d4++) {
                float4 kv = kr[d4];
                s += qreg[d4*4+0]*kv.x + qreg[d4*4+1]*kv.y
                   + qreg[d4*4+2]*kv.z + qreg[d4*4+3]*kv.w;
            }
            if (kg > qg || mask[b * SS + kg] == 0) s = -1e30f;
            p[j] = s;
            mt = fmaxf(mt, s);
        }
        mt = fmaxf(mt, __shfl_xor_sync(0xffffffffu, mt, 1));
        float mnew = fmaxf(mrow, mt);
        float corr = __expf(mrow - mnew);
        float ls = 0.f;
        #pragma unroll
        for (int j = 0; j < 32; j++) { p[j] = __expf(p[j] - mnew); ls += p[j]; }
        ls += __shfl_xor_sync(0xffffffffu, ls, 1);
        lrow = lrow * corr + ls;
        mrow = mnew;
        #pragma unroll
        for (int i = 0; i < 32; i++) O[i] *= corr;

        // PV: own 32 k's + partner's 32 (p via shfl within the pair)
        #pragma unroll
        for (int j = 0; j < 32; j++) {
            int ra = half * 32 + j;
            int rb = (half ^ 1) * 32 + j;
            float pa = p[j];
            float pb = __shfl_xor_sync(0xffffffffu, p[j], 1);
            const float4* va = (const float4*)(Vs + ra * 64 + half * 32);
            const float4* vb = (const float4*)(Vs + rb * 64 + half * 32);
            #pragma unroll
            for (int c = 0; c < 8; c++) {
                float4 x4 = va[c];
                O[c*4+0] += pa * x4.x; O[c*4+1] += pa * x4.y;
                O[c*4+2] += pa * x4.z; O[c*4+3] += pa * x4.w;
                float4 y4 = vb[c];
                O[c*4+0] += pb * y4.x; O[c*4+1] += pb * y4.y;
                O[c*4+2] += pb * y4.z; O[c*4+3] += pb * y4.w;
            }
        }
    }

    float inv = 1.f / lrow;
    float* orow = ctx + (size_t)(b * SS + qg) * DDIM + h * HDIM + half * 32;
    #pragma unroll
    for (int i = 0; i < 32; i++) orow[i] = tf32r(O[i] * inv);
}

// ---------------- launch ----------------
extern "C" void kernel_launch(void* const* d_in, const int* in_sizes, int n_in,
                              void* d_out, int out_size) {
    const float* x     = (const float*)d_in[0];
    const int*   amask = (const int*)  d_in[1];
    const float* wq    = (const float*)d_in[2];
    const float* wk    = (const float*)d_in[3];
    const float* wv    = (const float*)d_in[4];
    const float* wo    = (const float*)d_in[5];
    const float* bo    = (const float*)d_in[6];
    const float* ln1s  = (const float*)d_in[7];
    const float* ln1b  = (const float*)d_in[8];
    const float* ln2s  = (const float*)d_in[9];
    const float* ln2b  = (const float*)d_in[10];
    const float* w1    = (const float*)d_in[11];
    const float* b1    = (const float*)d_in[12];
    const float* w2    = (const float*)d_in[13];
    const float* b2    = (const float*)d_in[14];
    float* out = (float*)d_out;

    float *h, *qkv, *ctx, *x2, *mid, *wqkv, *wor, *w1r, *w2r;
    cudaGetSymbolAddress((void**)&h,    g_h);
    cudaGetSymbolAddress((void**)&qkv,  g_qkv);
    cudaGetSymbolAddress((void**)&ctx,  g_ctx);
    cudaGetSymbolAddress((void**)&x2,   g_x2);
    cudaGetSymbolAddress((void**)&mid,  g_mid);
    cudaGetSymbolAddress((void**)&wqkv, g_wqkv);
    cudaGetSymbolAddress((void**)&wor,  g_wo);
    cudaGetSymbolAddress((void**)&w1r,  g_w1);
    cudaGetSymbolAddress((void**)&w2r,  g_w2);

    // weight prep (unbiased tf32 rounding)
    round_concat_qkv<<<DDIM*3*DDIM/256, 256>>>(wq, wk, wv, wqkv);
    round_copy<<<DDIM*DDIM/256, 256>>>(wo, wor);
    round_copy<<<DDIM*DFF /256, 256>>>(w1, w1r);
    round_copy<<<DFF *DDIM/256, 256>>>(w2, w2r);

    // --- attention half ---
    ln_kernel<<<MTOT, 256>>>(x, ln1s, ln1b, h);
    gemm_kernel<0><<<dim3(3*DDIM/BN, MTOT/BM), 256>>>(h, wqkv, nullptr, nullptr,
                                                      qkv, MTOT, 3*DDIM, DDIM);
    attn_kernel<<<dim3(SS/64, HH, BB), 128>>>(qkv, amask, ctx);
    gemm_kernel<1><<<dim3(DDIM/BN, MTOT/BM), 256>>>(ctx, wor, bo, x,
                                                    x2, MTOT, DDIM, DDIM);

    // --- FFN half ---
    ln_kernel<<<MTOT, 256>>>(x2, ln2s, ln2b, h);
    gemm_kernel<2><<<dim3(DFF/BN, MTOT/BM), 256>>>(h, w1r, b1, nullptr,
                                                   mid, MTOT, DFF, DDIM);
    gemm_kernel<1><<<dim3(DDIM/BN, MTOT/BM), 256>>>(mid, w2r, b2, x2,
                                                    out, MTOT, DDIM, DFF);
}

// round 4
// speedup vs baseline: 1.6994x; 1.6994x over previous
#include <cuda_runtime.h>
#include <cstdint>

// ---------------- problem dims ----------------
#define BB 4
#define SS 1024
#define DDIM 1024
#define HH 16
#define HDIM 64
#define DFF 4096
#define MTOT (BB*SS)   // 4096

// ---------------- device scratch (no allocs allowed) ----------------
__device__ float g_h   [MTOT*DDIM];       // LN output (reused for ln1 and ln2)
__device__ float g_qkv [MTOT*3*DDIM];     // fused q|k|v
__device__ float g_ctx [MTOT*DDIM];
__device__ float g_x2  [MTOT*DDIM];
__device__ float g_mid [MTOT*DFF];

// ---------------- helpers ----------------
__device__ __forceinline__ float tf32r(float x) {
    uint32_t u;
    asm("cvt.rna.tf32.f32 %0, %1;" : "=r"(u) : "f"(x));
    return __uint_as_float(u);
}
__device__ __forceinline__ uint32_t tf32u(float x) {
    uint32_t u;
    asm("cvt.rna.tf32.f32 %0, %1;" : "=r"(u) : "f"(x));
    return u;
}

__device__ __forceinline__ void cp16(uint32_t dst, const void* src) {
    asm volatile("cp.async.cg.shared.global [%0], [%1], 16;" :: "r"(dst), "l"(src));
}
__device__ __forceinline__ void cpcommit() { asm volatile("cp.async.commit_group;"); }
template<int N> __device__ __forceinline__ void cpwait() {
    asm volatile("cp.async.wait_group %0;" :: "n"(N));
}

__device__ __forceinline__ float gelu_tanh(float v) {
    const float c = 0.79788456080286535588f;  // sqrt(2/pi)
    float u = c * (v + 0.044715f * v * v * v);
    return 0.5f * v * (1.f + tanhf(u));
}

// ---------------- LayerNorm (row = 1024), output rounded to tf32 ----------------
__global__ void ln_kernel(const float* __restrict__ x,
                          const float* __restrict__ scale,
                          const float* __restrict__ shift,
                          float* __restrict__ out) {
    int row = blockIdx.x;
    int t = threadIdx.x;                 // 256 threads, 4 floats each
    const float4* xr = (const float4*)(x + (size_t)row * DDIM);
    float4 v = xr[t];
    float s  = v.x + v.y + v.z + v.w;
    float s2 = v.x*v.x + v.y*v.y + v.z*v.z + v.w*v.w;
    #pragma unroll
    for (int o = 16; o >= 1; o >>= 1) {
        s  += __shfl_xor_sync(0xffffffffu, s,  o);
        s2 += __shfl_xor_sync(0xffffffffu, s2, o);
    }
    __shared__ float red[2][8];
    __shared__ float bcast[2];
    int wid = t >> 5, lane = t & 31;
    if (lane == 0) { red[0][wid] = s; red[1][wid] = s2; }
    __syncthreads();
    if (t == 0) {
        float S = 0.f, S2 = 0.f;
        #pragma unroll
        for (int i = 0; i < 8; i++) { S += red[0][i]; S2 += red[1][i]; }
        float m = S * (1.f / DDIM);
        float var = S2 * (1.f / DDIM) - m * m;
        bcast[0] = m;
        bcast[1] = rsqrtf(var + 1e-5f);
    }
    __syncthreads();
    float m = bcast[0], inv = bcast[1];
    float4 sc = ((const float4*)scale)[t];
    float4 sh = ((const float4*)shift)[t];
    float4 o;
    o.x = tf32r(sc.x * (v.x - m) * inv + sh.x);
    o.y = tf32r(sc.y * (v.y - m) * inv + sh.y);
    o.z = tf32r(sc.z * (v.z - m) * inv + sh.z);
    o.w = tf32r(sc.w * (v.w - m) * inv + sh.w);
    ((float4*)(out + (size_t)row * DDIM))[t] = o;
}

// ---------------- TF32 mma GEMM: C[M,N] = A[M,K] @ W[K,N] (+epilogue) ----------------
// A is pre-rounded tf32 (producer epilogues); W raw fp32, rounded in-register.
// EPI: 0 = plain fp32 store, 1 = +bias[n]+res[m,n], 2 = tf32r(gelu(acc+bias))
#define BM 128
#define BN 128
#define BKQ 16
#define AST 20      // A smem row stride (floats): 5x16B per row, coprime 8 -> LDSM conflict-free
#define BST 132     // B smem row stride
#define NSTAGE 4

#define A_STG_F (BM * AST)     // floats per A stage
#define B_STG_F (BKQ * BST)    // floats per B stage
#define GEMM_SMEM ((NSTAGE * (A_STG_F + B_STG_F)) * 4)   // 74752 bytes

template<int EPI>
__global__ void __launch_bounds__(256, 2) gemm_kernel(
    const float* __restrict__ A, const float* __restrict__ Wt,
    const float* __restrict__ bias, const float* __restrict__ res,
    float* __restrict__ C, int Kdim, int Bld, int Cld)
{
    extern __shared__ float smem[];
    float* As = smem;                       // NSTAGE * BM * AST
    float* Bs = smem + NSTAGE * A_STG_F;    // NSTAGE * BKQ * BST

    const int tid  = threadIdx.x;
    const int bm0  = blockIdx.y * BM;
    const int bn0  = blockIdx.x * BN;
    const int wid  = tid >> 5, lane = tid & 31;
    const int wm   = wid >> 2;      // 0..1  (M)
    const int wn   = wid & 3;       // 0..3  (N)
    const int g    = lane >> 2;     // groupID 0..7
    const int t4   = lane & 3;      // threadID_in_group

    float acc[4][4][4];
    #pragma unroll
    for (int i = 0; i < 4; i++)
        #pragma unroll
        for (int j = 0; j < 4; j++)
            #pragma unroll
            for (int c = 0; c < 4; c++) acc[i][j][c] = 0.f;

    // ---- global -> smem staging mapping ----
    const int arow = tid >> 2, ac4 = tid & 3;     // A: 128 rows x 4 float4; rows arow, arow+64
    const int brow = tid >> 5, bc4 = tid & 31;    // B: 16 rows x 32 float4; rows brow, brow+8
    const float* AgBase = A  + (size_t)(bm0 + arow) * Kdim + ac4 * 4;
    const float* BgBase = Wt + (size_t)brow * Bld + bn0 + bc4 * 4;
    const uint32_t AsW = (uint32_t)__cvta_generic_to_shared(&As[arow * AST + ac4 * 4]);
    const uint32_t BsW = (uint32_t)__cvta_generic_to_shared(&Bs[brow * BST + bc4 * 4]);

    // ---- ldmatrix lane address (A fragments) ----
    const int lrow = lane & 15;
    const int lcol = (lane >> 4) * 4;
    uint32_t aLd[4];
    #pragma unroll
    for (int i = 0; i < 4; i++)
        aLd[i] = (uint32_t)__cvta_generic_to_shared(
            &As[(wm * 64 + i * 16 + lrow) * AST + lcol]);

    const int KT = Kdim / BKQ;

    auto issue = [&](int kt) {
        const int   st = kt & (NSTAGE - 1);
        const float* Ag = AgBase + kt * BKQ;
        const float* Bg = BgBase + (size_t)kt * BKQ * Bld;
        uint32_t ad = AsW + st * (A_STG_F * 4);
        uint32_t bd = BsW + st * (B_STG_F * 4);
        cp16(ad,                Ag);
        cp16(ad + 64 * AST * 4, Ag + (size_t)64 * Kdim);
        cp16(bd,                Bg);
        cp16(bd + 8 * BST * 4,  Bg + (size_t)8 * Bld);
    };

    // prologue: stage tiles 0..NSTAGE-2
    #pragma unroll
    for (int s = 0; s < NSTAGE - 1; s++) { issue(s); cpcommit(); }

    for (int kt = 0; kt < KT; kt++) {
        cpwait<NSTAGE - 2>();
        __syncthreads();

        const int cb = kt & (NSTAGE - 1);
        const uint32_t aOff = cb * (A_STG_F * 4);
        const float* Bsc = Bs + cb * B_STG_F;

        #pragma unroll
        for (int k0 = 0; k0 < BKQ; k0 += 8) {
            uint32_t afr[4][4], bfr[4][2];
            #pragma unroll
            for (int i = 0; i < 4; i++) {
                asm volatile(
                    "ldmatrix.sync.aligned.m8n8.x4.shared.b16 {%0,%1,%2,%3}, [%4];"
                    : "=r"(afr[i][0]), "=r"(afr[i][1]),
                      "=r"(afr[i][2]), "=r"(afr[i][3])
                    : "r"(aLd[i] + aOff + k0 * 4));
            }
            #pragma unroll
            for (int j = 0; j < 4; j++) {
                int bc = wn * 32 + j * 8 + g;
                bfr[j][0] = tf32u(Bsc[(k0 + t4) * BST + bc]);
                bfr[j][1] = tf32u(Bsc[(k0 + t4 + 4) * BST + bc]);
            }
            #pragma unroll
            for (int i = 0; i < 4; i++)
                #pragma unroll
                for (int j = 0; j < 4; j++) {
                    asm volatile(
                        "mma.sync.aligned.m16n8k8.row.col.f32.tf32.tf32.f32 "
                        "{%0,%1,%2,%3},{%4,%5,%6,%7},{%8,%9},{%0,%1,%2,%3};\n"
                        : "+f"(acc[i][j][0]), "+f"(acc[i][j][1]),
                          "+f"(acc[i][j][2]), "+f"(acc[i][j][3])
                        : "r"(afr[i][0]), "r"(afr[i][1]), "r"(afr[i][2]), "r"(afr[i][3]),
                          "r"(bfr[j][0]), "r"(bfr[j][1]));
                }
        }
        __syncthreads();
        if (kt + NSTAGE - 1 < KT) issue(kt + NSTAGE - 1);
        cpcommit();
    }

    // ---- epilogue (float2 stores) ----
    #pragma unroll
    for (int i = 0; i < 4; i++) {
        #pragma unroll
        for (int j = 0; j < 4; j++) {
            int r0 = bm0 + wm * 64 + i * 16 + g;
            int c0 = bn0 + wn * 32 + j * 8 + t4 * 2;
            #pragma unroll
            for (int half = 0; half < 2; half++) {
                int r = r0 + half * 8;
                float2 v = make_float2(acc[i][j][half * 2], acc[i][j][half * 2 + 1]);
                if (EPI == 1) {
                    float2 rr = *(const float2*)(res + (size_t)r * Cld + c0);
                    v.x = v.x + bias[c0]     + rr.x;
                    v.y = v.y + bias[c0 + 1] + rr.y;
                }
                if (EPI == 2) {
                    v.x = tf32r(gelu_tanh(v.x + bias[c0]));
                    v.y = tf32r(gelu_tanh(v.y + bias[c0 + 1]));
                }
                *(float2*)(C + (size_t)r * Cld + c0) = v;
            }
        }
    }
}

// ---------------- fused causal flash attention (fp32) ----------------
// grid (S/64, H, B), 128 threads. Thread pair (2q,2q+1): q-row split across
// k-halves (scores) and d-halves (output). qkv layout: [b,s, q|k|v of 1024 each].
__global__ void __launch_bounds__(128) attn_kernel(
    const float* __restrict__ qkv, const int* __restrict__ mask,
    float* __restrict__ ctx)
{
    __shared__ float Ks[64 * 64];
    __shared__ float Vs[64 * 64];

    const int b = blockIdx.z, h = blockIdx.y, q0 = blockIdx.x * 64;
    const int t = threadIdx.x;
    const int qr = t >> 1, half = t & 1;
    const int qg = q0 + qr;

    const float* qrow = qkv + (size_t)(b * SS + qg) * 3 * DDIM + h * HDIM;
    float qreg[64];
    #pragma unroll
    for (int d4 = 0; d4 < 16; d4++) {
        float4 qv = ((const float4*)qrow)[d4];
        qreg[d4*4+0] = qv.x * 0.125f;  // 1/sqrt(64)
        qreg[d4*4+1] = qv.y * 0.125f;
        qreg[d4*4+2] = qv.z * 0.125f;
        qreg[d4*4+3] = qv.w * 0.125f;
    }

    float O[32];
    #pragma unroll
    for (int i = 0; i < 32; i++) O[i] = 0.f;
    float mrow = -1e30f, lrow = 0.f;

    const int ntiles = q0 / 64 + 1;
    for (int kt = 0; kt < ntiles; kt++) {
        __syncthreads();
        {   // cooperative K/V tile load: 64 rows x 16 float4 each
            size_t base = (size_t)(b * SS + kt * 64) * 3 * DDIM + h * HDIM;
            for (int i = t; i < 64 * 16; i += 128) {
                int row = i >> 4, c4 = i & 15;
                ((float4*)Ks)[row * 16 + c4] =
                    *(const float4*)(qkv + base + (size_t)row * 3 * DDIM + DDIM + c4 * 4);
                ((float4*)Vs)[row * 16 + c4] =
                    *(const float4*)(qkv + base + (size_t)row * 3 * DDIM + 2 * DDIM + c4 * 4);
            }
        }
        __syncthreads();

        float p[32];
        float mt = -1e30f;
        #pragma unroll
        for (int j = 0; j < 32; j++) {
            int kk = half * 32 + j;
            int kg = kt * 64 + kk;
            const float4* kr = (const float4*)(Ks + kk * 64);
            float s = 0.f;
            #pragma unroll
            for (int d4 = 0; d4 < 16; d4++) {
                float4 kv = kr[d4];
                s += qreg[d4*4+0]*kv.x + qreg[d4*4+1]*kv.y
                   + qreg[d4*4+2]*kv.z + qreg[d4*4+3]*kv.w;
            }
            if (kg > qg || mask[b * SS + kg] == 0) s = -1e30f;
            p[j] = s;
            mt = fmaxf(mt, s);
        }
        mt = fmaxf(mt, __shfl_xor_sync(0xffffffffu, mt, 1));
        float mnew = fmaxf(mrow, mt);
        float corr = __expf(mrow - mnew);
        float ls = 0.f;
        #pragma unroll
        for (int j = 0; j < 32; j++) { p[j] = __expf(p[j] - mnew); ls += p[j]; }
        ls += __shfl_xor_sync(0xffffffffu, ls, 1);
        lrow = lrow * corr + ls;
        mrow = mnew;
        #pragma unroll
        for (int i = 0; i < 32; i++) O[i] *= corr;

        // PV: own 32 k's + partner's 32 (p via shfl within the pair)
        #pragma unroll
        for (int j = 0; j < 32; j++) {
            int ra = half * 32 + j;
            int rb = (half ^ 1) * 32 + j;
            float pa = p[j];
            float pb = __shfl_xor_sync(0xffffffffu, p[j], 1);
            const float4* va = (const float4*)(Vs + ra * 64 + half * 32);
            const float4* vb = (const float4*)(Vs + rb * 64 + half * 32);
            #pragma unroll
            for (int c = 0; c < 8; c++) {
                float4 x4 = va[c];
                O[c*4+0] += pa * x4.x; O[c*4+1] += pa * x4.y;
                O[c*4+2] += pa * x4.z; O[c*4+3] += pa * x4.w;
                float4 y4 = vb[c];
                O[c*4+0] += pb * y4.x; O[c*4+1] += pb * y4.y;
                O[c*4+2] += pb * y4.z; O[c*4+3] += pb * y4.w;
            }
        }
    }

    float inv = 1.f / lrow;
    float* orow = ctx + (size_t)(b * SS + qg) * DDIM + h * HDIM + half * 32;
    #pragma unroll
    for (int i = 0; i < 32; i++) orow[i] = tf32r(O[i] * inv);
}

// ---------------- launch ----------------
extern "C" void kernel_launch(void* const* d_in, const int* in_sizes, int n_in,
                              void* d_out, int out_size) {
    const float* x     = (const float*)d_in[0];
    const int*   amask = (const int*)  d_in[1];
    const float* wq    = (const float*)d_in[2];
    const float* wk    = (const float*)d_in[3];
    const float* wv    = (const float*)d_in[4];
    const float* wo    = (const float*)d_in[5];
    const float* bo    = (const float*)d_in[6];
    const float* ln1s  = (const float*)d_in[7];
    const float* ln1b  = (const float*)d_in[8];
    const float* ln2s  = (const float*)d_in[9];
    const float* ln2b  = (const float*)d_in[10];
    const float* w1    = (const float*)d_in[11];
    const float* b1    = (const float*)d_in[12];
    const float* w2    = (const float*)d_in[13];
    const float* b2    = (const float*)d_in[14];
    float* out = (float*)d_out;

    float *h, *qkv, *ctx, *x2, *mid;
    cudaGetSymbolAddress((void**)&h,   g_h);
    cudaGetSymbolAddress((void**)&qkv, g_qkv);
    cudaGetSymbolAddress((void**)&ctx, g_ctx);
    cudaGetSymbolAddress((void**)&x2,  g_x2);
    cudaGetSymbolAddress((void**)&mid, g_mid);

    cudaFuncSetAttribute(gemm_kernel<0>, cudaFuncAttributeMaxDynamicSharedMemorySize, GEMM_SMEM);
    cudaFuncSetAttribute(gemm_kernel<1>, cudaFuncAttributeMaxDynamicSharedMemorySize, GEMM_SMEM);
    cudaFuncSetAttribute(gemm_kernel<2>, cudaFuncAttributeMaxDynamicSharedMemorySize, GEMM_SMEM);

    // --- attention half ---
    ln_kernel<<<MTOT, 256>>>(x, ln1s, ln1b, h);
    // QKV: three gemms into the strided concat buffer qkv[m][3072]
    gemm_kernel<0><<<dim3(DDIM/BN, MTOT/BM), 256, GEMM_SMEM>>>(
        h, wq, nullptr, nullptr, qkv + 0,        DDIM, DDIM, 3*DDIM);
    gemm_kernel<0><<<dim3(DDIM/BN, MTOT/BM), 256, GEMM_SMEM>>>(
        h, wk, nullptr, nullptr, qkv + DDIM,     DDIM, DDIM, 3*DDIM);
    gemm_kernel<0><<<dim3(DDIM/BN, MTOT/BM), 256, GEMM_SMEM>>>(
        h, wv, nullptr, nullptr, qkv + 2*DDIM,   DDIM, DDIM, 3*DDIM);
    attn_kernel<<<dim3(SS/64, HH, BB), 128>>>(qkv, amask, ctx);
    gemm_kernel<1><<<dim3(DDIM/BN, MTOT/BM), 256, GEMM_SMEM>>>(
        ctx, wo, bo, x, x2, DDIM, DDIM, DDIM);

    // --- FFN half ---
    ln_kernel<<<MTOT, 256>>>(x2, ln2s, ln2b, h);
    gemm_kernel<2><<<dim3(DFF/BN, MTOT/BM), 256, GEMM_SMEM>>>(
        h, w1, b1, nullptr, mid, DDIM, DFF, DFF);
    gemm_kernel<1><<<dim3(DDIM/BN, MTOT/BM), 256, GEMM_SMEM>>>(
        mid, w2, b2, x2, out, DFF, DDIM, DDIM);
}

// round 5
// speedup vs baseline: 1.8330x; 1.0786x over previous
#include <cuda_runtime.h>
#include <cstdint>

// ---------------- problem dims ----------------
#define BB 4
#define SS 1024
#define DDIM 1024
#define HH 16
#define HDIM 64
#define DFF 4096
#define MTOT (BB*SS)   // 4096

// ---------------- device scratch (no allocs allowed) ----------------
__device__ float g_h   [MTOT*DDIM];       // LN output (reused for ln1 and ln2)
__device__ float g_qkv [MTOT*3*DDIM];     // fused q|k|v
__device__ float g_ctx [MTOT*DDIM];
__device__ float g_x2  [MTOT*DDIM];
__device__ float g_mid [MTOT*DFF];

// ---------------- helpers ----------------
__device__ __forceinline__ float tf32r(float x) {
    uint32_t u;
    asm("cvt.rna.tf32.f32 %0, %1;" : "=r"(u) : "f"(x));
    return __uint_as_float(u);
}
__device__ __forceinline__ uint32_t tf32u(float x) {
    uint32_t u;
    asm("cvt.rna.tf32.f32 %0, %1;" : "=r"(u) : "f"(x));
    return u;
}

__device__ __forceinline__ void cp16(uint32_t dst, const void* src) {
    asm volatile("cp.async.cg.shared.global [%0], [%1], 16;" :: "r"(dst), "l"(src));
}
__device__ __forceinline__ void cpcommit() { asm volatile("cp.async.commit_group;"); }
template<int N> __device__ __forceinline__ void cpwait() {
    asm volatile("cp.async.wait_group %0;" :: "n"(N));
}

__device__ __forceinline__ float gelu_tanh(float v) {
    const float c = 0.79788456080286535588f;  // sqrt(2/pi)
    float u = c * (v + 0.044715f * v * v * v);
    return 0.5f * v * (1.f + tanhf(u));
}

// ---------------- LayerNorm (row = 1024), output rounded to tf32 ----------------
__global__ void ln_kernel(const float* __restrict__ x,
                          const float* __restrict__ scale,
                          const float* __restrict__ shift,
                          float* __restrict__ out) {
    int row = blockIdx.x;
    int t = threadIdx.x;                 // 256 threads, 4 floats each
    const float4* xr = (const float4*)(x + (size_t)row * DDIM);
    float4 v = xr[t];
    float s  = v.x + v.y + v.z + v.w;
    float s2 = v.x*v.x + v.y*v.y + v.z*v.z + v.w*v.w;
    #pragma unroll
    for (int o = 16; o >= 1; o >>= 1) {
        s  += __shfl_xor_sync(0xffffffffu, s,  o);
        s2 += __shfl_xor_sync(0xffffffffu, s2, o);
    }
    __shared__ float red[2][8];
    __shared__ float bcast[2];
    int wid = t >> 5, lane = t & 31;
    if (lane == 0) { red[0][wid] = s; red[1][wid] = s2; }
    __syncthreads();
    if (t == 0) {
        float S = 0.f, S2 = 0.f;
        #pragma unroll
        for (int i = 0; i < 8; i++) { S += red[0][i]; S2 += red[1][i]; }
        float m = S * (1.f / DDIM);
        float var = S2 * (1.f / DDIM) - m * m;
        bcast[0] = m;
        bcast[1] = rsqrtf(var + 1e-5f);
    }
    __syncthreads();
    float m = bcast[0], inv = bcast[1];
    float4 sc = ((const float4*)scale)[t];
    float4 sh = ((const float4*)shift)[t];
    float4 o;
    o.x = tf32r(sc.x * (v.x - m) * inv + sh.x);
    o.y = tf32r(sc.y * (v.y - m) * inv + sh.y);
    o.z = tf32r(sc.z * (v.z - m) * inv + sh.z);
    o.w = tf32r(sc.w * (v.w - m) * inv + sh.w);
    ((float4*)(out + (size_t)row * DDIM))[t] = o;
}

// ---------------- TF32 mma GEMM: C[M,N] = A[M,K] @ W[K,N] (+epilogue) ----------------
// A is pre-rounded tf32 (producer epilogues); W raw fp32, rounded in-register.
// EPI: 0 = plain fp32 store, 1 = +bias[n]+res[m,n], 2 = tf32r(gelu(acc+bias))
#define BM 128
#define BN 128
#define BKQ 32
#define AST 36      // A smem row stride (floats): rows at 144B -> 8 distinct 16B banks per LDSM phase
#define BST 136     // B smem row stride: bank = 8*t4+g -> full 32-lane permutation, conflict-free
#define NSTAGE 2

#define A_STG_F (BM * AST)     // floats per A stage (4608)
#define B_STG_F (BKQ * BST)    // floats per B stage (4352)
#define GEMM_SMEM ((NSTAGE * (A_STG_F + B_STG_F)) * 4)   // 71680 bytes

template<int EPI>
__global__ void __launch_bounds__(256, 2) gemm_kernel(
    const float* __restrict__ A, const float* __restrict__ Wt,
    const float* __restrict__ bias, const float* __restrict__ res,
    float* __restrict__ C, int Kdim, int Bld, int Cld)
{
    extern __shared__ float smem[];
    float* As = smem;                       // NSTAGE * BM * AST
    float* Bs = smem + NSTAGE * A_STG_F;    // NSTAGE * BKQ * BST

    const int tid  = threadIdx.x;
    const int bm0  = blockIdx.y * BM;
    const int bn0  = blockIdx.x * BN;
    const int wid  = tid >> 5, lane = tid & 31;
    const int wm   = wid >> 2;      // 0..1  (M)
    const int wn   = wid & 3;       // 0..3  (N)
    const int g    = lane >> 2;     // groupID 0..7
    const int t4   = lane & 3;      // threadID_in_group

    float acc[4][4][4];
    #pragma unroll
    for (int i = 0; i < 4; i++)
        #pragma unroll
        for (int j = 0; j < 4; j++)
            #pragma unroll
            for (int c = 0; c < 4; c++) acc[i][j][c] = 0.f;

    // ---- global -> smem staging mapping (8 cp16 per thread per stage) ----
    const int arow = tid >> 3, ac8 = tid & 7;     // A: 128 rows x 8 float4; rows arow + {0,32,64,96}
    const int brow = tid >> 5, bc4 = tid & 31;    // B: 32 rows x 32 float4; rows brow + {0,8,16,24}
    const float* AgBase = A  + (size_t)(bm0 + arow) * Kdim + ac8 * 4;
    const float* BgBase = Wt + (size_t)brow * Bld + bn0 + bc4 * 4;
    const uint32_t AsW = (uint32_t)__cvta_generic_to_shared(&As[arow * AST + ac8 * 4]);
    const uint32_t BsW = (uint32_t)__cvta_generic_to_shared(&Bs[brow * BST + bc4 * 4]);

    // ---- ldmatrix lane address (A fragments) ----
    const int lrow = lane & 15;
    const int lcol = (lane >> 4) * 4;
    uint32_t aLd[4];
    #pragma unroll
    for (int i = 0; i < 4; i++)
        aLd[i] = (uint32_t)__cvta_generic_to_shared(
            &As[(wm * 64 + i * 16 + lrow) * AST + lcol]);

    const int KT = Kdim / BKQ;

    auto issue = [&](int kt) {
        const int   st = kt & (NSTAGE - 1);
        const float* Ag = AgBase + kt * BKQ;
        const float* Bg = BgBase + (size_t)kt * BKQ * Bld;
        uint32_t ad = AsW + st * (A_STG_F * 4);
        uint32_t bd = BsW + st * (B_STG_F * 4);
        #pragma unroll
        for (int r = 0; r < 4; r++) {
            cp16(ad + r * 32 * AST * 4, Ag + (size_t)(r * 32) * Kdim);
            cp16(bd + r * 8  * BST * 4, Bg + (size_t)(r * 8)  * Bld);
        }
    };

    // prologue: stage tile 0
    issue(0); cpcommit();

    for (int kt = 0; kt < KT; kt++) {
        cpwait<0>();
        __syncthreads();          // data visible + everyone done with prev buffer

        if (kt + 1 < KT) issue(kt + 1);   // overlaps with mma below
        cpcommit();

        const int cb = kt & (NSTAGE - 1);
        const uint32_t aOff = cb * (A_STG_F * 4);
        const float* Bsc = Bs + cb * B_STG_F;

        #pragma unroll
        for (int k0 = 0; k0 < BKQ; k0 += 8) {
            uint32_t afr[4][4], bfr[4][2];
            #pragma unroll
            for (int i = 0; i < 4; i++) {
                asm volatile(
                    "ldmatrix.sync.aligned.m8n8.x4.shared.b16 {%0,%1,%2,%3}, [%4];"
                    : "=r"(afr[i][0]), "=r"(afr[i][1]),
                      "=r"(afr[i][2]), "=r"(afr[i][3])
                    : "r"(aLd[i] + aOff + k0 * 4));
            }
            #pragma unroll
            for (int j = 0; j < 4; j++) {
                int bc = wn * 32 + j * 8 + g;
                bfr[j][0] = tf32u(Bsc[(k0 + t4) * BST + bc]);
                bfr[j][1] = tf32u(Bsc[(k0 + t4 + 4) * BST + bc]);
            }
            #pragma unroll
            for (int i = 0; i < 4; i++)
                #pragma unroll
                for (int j = 0; j < 4; j++) {
                    asm volatile(
                        "mma.sync.aligned.m16n8k8.row.col.f32.tf32.tf32.f32 "
                        "{%0,%1,%2,%3},{%4,%5,%6,%7},{%8,%9},{%0,%1,%2,%3};\n"
                        : "+f"(acc[i][j][0]), "+f"(acc[i][j][1]),
                          "+f"(acc[i][j][2]), "+f"(acc[i][j][3])
                        : "r"(afr[i][0]), "r"(afr[i][1]), "r"(afr[i][2]), "r"(afr[i][3]),
                          "r"(bfr[j][0]), "r"(bfr[j][1]));
                }
        }
        __syncthreads();          // everyone done reading cb before it is refilled
    }

    // ---- epilogue (float2 stores) ----
    #pragma unroll
    for (int i = 0; i < 4; i++) {
        #pragma unroll
        for (int j = 0; j < 4; j++) {
            int r0 = bm0 + wm * 64 + i * 16 + g;
            int c0 = bn0 + wn * 32 + j * 8 + t4 * 2;
            #pragma unroll
            for (int half = 0; half < 2; half++) {
                int r = r0 + half * 8;
                float2 v = make_float2(acc[i][j][half * 2], acc[i][j][half * 2 + 1]);
                if (EPI == 1) {
                    float2 rr = *(const float2*)(res + (size_t)r * Cld + c0);
                    v.x = v.x + bias[c0]     + rr.x;
                    v.y = v.y + bias[c0 + 1] + rr.y;
                }
                if (EPI == 2) {
                    v.x = tf32r(gelu_tanh(v.x + bias[c0]));
                    v.y = tf32r(gelu_tanh(v.y + bias[c0 + 1]));
                }
                *(float2*)(C + (size_t)r * Cld + c0) = v;
            }
        }
    }
}

// ---------------- fused causal flash attention (fp32) ----------------
// grid (S/64, H, B), 128 threads. Thread pair (2q,2q+1): q-row split across
// k-halves (scores) and d-halves (output). qkv layout: [b,s, q|k|v of 1024 each].
__global__ void __launch_bounds__(128) attn_kernel(
    const float* __restrict__ qkv, const int* __restrict__ mask,
    float* __restrict__ ctx)
{
    __shared__ float Ks[64 * 64];
    __shared__ float Vs[64 * 64];

    const int b = blockIdx.z, h = blockIdx.y, q0 = blockIdx.x * 64;
    const int t = threadIdx.x;
    const int qr = t >> 1, half = t & 1;
    const int qg = q0 + qr;

    const float* qrow = qkv + (size_t)(b * SS + qg) * 3 * DDIM + h * HDIM;
    float qreg[64];
    #pragma unroll
    for (int d4 = 0; d4 < 16; d4++) {
        float4 qv = ((const float4*)qrow)[d4];
        qreg[d4*4+0] = qv.x * 0.125f;  // 1/sqrt(64)
        qreg[d4*4+1] = qv.y * 0.125f;
        qreg[d4*4+2] = qv.z * 0.125f;
        qreg[d4*4+3] = qv.w * 0.125f;
    }

    float O[32];
    #pragma unroll
    for (int i = 0; i < 32; i++) O[i] = 0.f;
    float mrow = -1e30f, lrow = 0.f;

    const int ntiles = q0 / 64 + 1;
    for (int kt = 0; kt < ntiles; kt++) {
        __syncthreads();
        {   // cooperative K/V tile load: 64 rows x 16 float4 each
            size_t base = (size_t)(b * SS + kt * 64) * 3 * DDIM + h * HDIM;
            for (int i = t; i < 64 * 16; i += 128) {
                int row = i >> 4, c4 = i & 15;
                ((float4*)Ks)[row * 16 + c4] =
                    *(const float4*)(qkv + base + (size_t)row * 3 * DDIM + DDIM + c4 * 4);
                ((float4*)Vs)[row * 16 + c4] =
                    *(const float4*)(qkv + base + (size_t)row * 3 * DDIM + 2 * DDIM + c4 * 4);
            }
        }
        __syncthreads();

        float p[32];
        float mt = -1e30f;
        #pragma unroll
        for (int j = 0; j < 32; j++) {
            int kk = half * 32 + j;
            int kg = kt * 64 + kk;
            const float4* kr = (const float4*)(Ks + kk * 64);
            float s = 0.f;
            #pragma unroll
            for (int d4 = 0; d4 < 16; d4++) {
                float4 kv = kr[d4];
                s += qreg[d4*4+0]*kv.x + qreg[d4*4+1]*kv.y
                   + qreg[d4*4+2]*kv.z + qreg[d4*4+3]*kv.w;
            }
            if (kg > qg || mask[b * SS + kg] == 0) s = -1e30f;
            p[j] = s;
            mt = fmaxf(mt, s);
        }
        mt = fmaxf(mt, __shfl_xor_sync(0xffffffffu, mt, 1));
        float mnew = fmaxf(mrow, mt);
        float corr = __expf(mrow - mnew);
        float ls = 0.f;
        #pragma unroll
        for (int j = 0; j < 32; j++) { p[j] = __expf(p[j] - mnew); ls += p[j]; }
        ls += __shfl_xor_sync(0xffffffffu, ls, 1);
        lrow = lrow * corr + ls;
        mrow = mnew;
        #pragma unroll
        for (int i = 0; i < 32; i++) O[i] *= corr;

        // PV: own 32 k's + partner's 32 (p via shfl within the pair)
        #pragma unroll
        for (int j = 0; j < 32; j++) {
            int ra = half * 32 + j;
            int rb = (half ^ 1) * 32 + j;
            float pa = p[j];
            float pb = __shfl_xor_sync(0xffffffffu, p[j], 1);
            const float4* va = (const float4*)(Vs + ra * 64 + half * 32);
            const float4* vb = (const float4*)(Vs + rb * 64 + half * 32);
            #pragma unroll
            for (int c = 0; c < 8; c++) {
                float4 x4 = va[c];
                O[c*4+0] += pa * x4.x; O[c*4+1] += pa * x4.y;
                O[c*4+2] += pa * x4.z; O[c*4+3] += pa * x4.w;
                float4 y4 = vb[c];
                O[c*4+0] += pb * y4.x; O[c*4+1] += pb * y4.y;
                O[c*4+2] += pb * y4.z; O[c*4+3] += pb * y4.w;
            }
        }
    }

    float inv = 1.f / lrow;
    float* orow = ctx + (size_t)(b * SS + qg) * DDIM + h * HDIM + half * 32;
    #pragma unroll
    for (int i = 0; i < 32; i++) orow[i] = tf32r(O[i] * inv);
}

// ---------------- launch ----------------
extern "C" void kernel_launch(void* const* d_in, const int* in_sizes, int n_in,
                              void* d_out, int out_size) {
    const float* x     = (const float*)d_in[0];
    const int*   amask = (const int*)  d_in[1];
    const float* wq    = (const float*)d_in[2];
    const float* wk    = (const float*)d_in[3];
    const float* wv    = (const float*)d_in[4];
    const float* wo    = (const float*)d_in[5];
    const float* bo    = (const float*)d_in[6];
    const float* ln1s  = (const float*)d_in[7];
    const float* ln1b  = (const float*)d_in[8];
    const float* ln2s  = (const float*)d_in[9];
    const float* ln2b  = (const float*)d_in[10];
    const float* w1    = (const float*)d_in[11];
    const float* b1    = (const float*)d_in[12];
    const float* w2    = (const float*)d_in[13];
    const float* b2    = (const float*)d_in[14];
    float* out = (float*)d_out;

    float *h, *qkv, *ctx, *x2, *mid;
    cudaGetSymbolAddress((void**)&h,   g_h);
    cudaGetSymbolAddress((void**)&qkv, g_qkv);
    cudaGetSymbolAddress((void**)&ctx, g_ctx);
    cudaGetSymbolAddress((void**)&x2,  g_x2);
    cudaGetSymbolAddress((void**)&mid, g_mid);

    cudaFuncSetAttribute(gemm_kernel<0>, cudaFuncAttributeMaxDynamicSharedMemorySize, GEMM_SMEM);
    cudaFuncSetAttribute(gemm_kernel<1>, cudaFuncAttributeMaxDynamicSharedMemorySize, GEMM_SMEM);
    cudaFuncSetAttribute(gemm_kernel<2>, cudaFuncAttributeMaxDynamicSharedMemorySize, GEMM_SMEM);

    // --- attention half ---
    ln_kernel<<<MTOT, 256>>>(x, ln1s, ln1b, h);
    // QKV: three gemms into the strided concat buffer qkv[m][3072]
    gemm_kernel<0><<<dim3(DDIM/BN, MTOT/BM), 256, GEMM_SMEM>>>(
        h, wq, nullptr, nullptr, qkv + 0,        DDIM, DDIM, 3*DDIM);
    gemm_kernel<0><<<dim3(DDIM/BN, MTOT/BM), 256, GEMM_SMEM>>>(
        h, wk, nullptr, nullptr, qkv + DDIM,     DDIM, DDIM, 3*DDIM);
    gemm_kernel<0><<<dim3(DDIM/BN, MTOT/BM), 256, GEMM_SMEM>>>(
        h, wv, nullptr, nullptr, qkv + 2*DDIM,   DDIM, DDIM, 3*DDIM);
    attn_kernel<<<dim3(SS/64, HH, BB), 128>>>(qkv, amask, ctx);
    gemm_kernel<1><<<dim3(DDIM/BN, MTOT/BM), 256, GEMM_SMEM>>>(
        ctx, wo, bo, x, x2, DDIM, DDIM, DDIM);

    // --- FFN half ---
    ln_kernel<<<MTOT, 256>>>(x2, ln2s, ln2b, h);
    gemm_kernel<2><<<dim3(DFF/BN, MTOT/BM), 256, GEMM_SMEM>>>(
        h, w1, b1, nullptr, mid, DDIM, DFF, DFF);
    gemm_kernel<1><<<dim3(DDIM/BN, MTOT/BM), 256, GEMM_SMEM>>>(
        mid, w2, b2, x2, out, DFF, DDIM, DDIM);
}

// round 8
// speedup vs baseline: 2.8408x; 1.5498x over previous
#include <cuda_runtime.h>
#include <cstdint>

// ---------------- problem dims ----------------
#define BB 4
#define SS 1024
#define DDIM 1024
#define HH 16
#define HDIM 64
#define DFF 4096
#define MTOT (BB*SS)   // 4096

// ---------------- device scratch (no allocs allowed) ----------------
__device__ float g_h   [MTOT*DDIM];
__device__ float g_qkv [(size_t)MTOT*3*DDIM];
__device__ float g_ctx [MTOT*DDIM];
__device__ float g_x2  [MTOT*DDIM];
__device__ float g_mid [(size_t)MTOT*DFF];

// ---------------- helpers ----------------
__device__ __forceinline__ float tf32r(float x) {
    uint32_t u;
    asm("cvt.rna.tf32.f32 %0, %1;" : "=r"(u) : "f"(x));
    return __uint_as_float(u);
}
__device__ __forceinline__ uint32_t tf32u(float x) {
    uint32_t u;
    asm("cvt.rna.tf32.f32 %0, %1;" : "=r"(u) : "f"(x));
    return u;
}
__device__ __forceinline__ void cp16(uint32_t dst, const void* src) {
    asm volatile("cp.async.cg.shared.global [%0], [%1], 16;" :: "r"(dst), "l"(src));
}
__device__ __forceinline__ void cpcommit() { asm volatile("cp.async.commit_group;"); }
template<int N> __device__ __forceinline__ void cpwait() {
    asm volatile("cp.async.wait_group %0;" :: "n"(N));
}
__device__ __forceinline__ float gelu_tanh(float v) {
    const float c = 0.79788456080286535588f;  // sqrt(2/pi)
    float u = c * (v + 0.044715f * v * v * v);
    return 0.5f * v * (1.f + tanhf(u));
}

#define MMA_TF32(acc, a0,a1,a2,a3, b0,b1) \
    asm volatile( \
        "mma.sync.aligned.m16n8k8.row.col.f32.tf32.tf32.f32 " \
        "{%0,%1,%2,%3},{%4,%5,%6,%7},{%8,%9},{%0,%1,%2,%3};\n" \
        : "+f"((acc)[0]), "+f"((acc)[1]), "+f"((acc)[2]), "+f"((acc)[3]) \
        : "r"(a0), "r"(a1), "r"(a2), "r"(a3), "r"(b0), "r"(b1))

// ---------------- LayerNorm (row = 1024), output rounded to tf32 ----------------
__global__ void ln_kernel(const float* __restrict__ x,
                          const float* __restrict__ scale,
                          const float* __restrict__ shift,
                          float* __restrict__ out) {
    int row = blockIdx.x;
    int t = threadIdx.x;                 // 256 threads, 4 floats each
    const float4* xr = (const float4*)(x + (size_t)row * DDIM);
    float4 v = xr[t];
    float s  = v.x + v.y + v.z + v.w;
    float s2 = v.x*v.x + v.y*v.y + v.z*v.z + v.w*v.w;
    #pragma unroll
    for (int o = 16; o >= 1; o >>= 1) {
        s  += __shfl_xor_sync(0xffffffffu, s,  o);
        s2 += __shfl_xor_sync(0xffffffffu, s2, o);
    }
    __shared__ float red[2][8];
    __shared__ float bcast[2];
    int wid = t >> 5, lane = t & 31;
    if (lane == 0) { red[0][wid] = s; red[1][wid] = s2; }
    __syncthreads();
    if (t == 0) {
        float S = 0.f, S2 = 0.f;
        #pragma unroll
        for (int i = 0; i < 8; i++) { S += red[0][i]; S2 += red[1][i]; }
        float m = S * (1.f / DDIM);
        float var = S2 * (1.f / DDIM) - m * m;
        bcast[0] = m;
        bcast[1] = rsqrtf(var + 1e-5f);
    }
    __syncthreads();
    float m = bcast[0], inv = bcast[1];
    float4 sc = ((const float4*)scale)[t];
    float4 sh = ((const float4*)shift)[t];
    float4 o;
    o.x = tf32r(sc.x * (v.x - m) * inv + sh.x);
    o.y = tf32r(sc.y * (v.y - m) * inv + sh.y);
    o.z = tf32r(sc.z * (v.z - m) * inv + sh.z);
    o.w = tf32r(sc.w * (v.w - m) * inv + sh.w);
    ((float4*)(out + (size_t)row * DDIM))[t] = o;
}

// ---------------- TF32 mma GEMM (proven R5 kernel, unchanged) ----------------
#define BM 128
#define BN 128
#define BKQ 32
#define AST 36
#define BST 136
#define NSTAGE 2

#define A_STG_F (BM * AST)
#define B_STG_F (BKQ * BST)
#define GEMM_SMEM ((NSTAGE * (A_STG_F + B_STG_F)) * 4)

template<int EPI>
__global__ void __launch_bounds__(256, 2) gemm_kernel(
    const float* __restrict__ A, const float* __restrict__ Wt,
    const float* __restrict__ bias, const float* __restrict__ res,
    float* __restrict__ C, int Kdim, int Bld, int Cld)
{
    extern __shared__ float smem[];
    float* As = smem;
    float* Bs = smem + NSTAGE * A_STG_F;

    const int tid  = threadIdx.x;
    const int bm0  = blockIdx.y * BM;
    const int bn0  = blockIdx.x * BN;
    const int wid  = tid >> 5, lane = tid & 31;
    const int wm   = wid >> 2;
    const int wn   = wid & 3;
    const int g    = lane >> 2;
    const int t4   = lane & 3;

    float acc[4][4][4];
    #pragma unroll
    for (int i = 0; i < 4; i++)
        #pragma unroll
        for (int j = 0; j < 4; j++)
            #pragma unroll
            for (int c = 0; c < 4; c++) acc[i][j][c] = 0.f;

    const int arow = tid >> 3, ac8 = tid & 7;
    const int brow = tid >> 5, bc4 = tid & 31;
    const float* AgBase = A  + (size_t)(bm0 + arow) * Kdim + ac8 * 4;
    const float* BgBase = Wt + (size_t)brow * Bld + bn0 + bc4 * 4;
    const uint32_t AsW = (uint32_t)__cvta_generic_to_shared(&As[arow * AST + ac8 * 4]);
    const uint32_t BsW = (uint32_t)__cvta_generic_to_shared(&Bs[brow * BST + bc4 * 4]);

    const int lrow = lane & 15;
    const int lcol = (lane >> 4) * 4;
    uint32_t aLd[4];
    #pragma unroll
    for (int i = 0; i < 4; i++)
        aLd[i] = (uint32_t)__cvta_generic_to_shared(
            &As[(wm * 64 + i * 16 + lrow) * AST + lcol]);

    const int KT = Kdim / BKQ;

    auto issue = [&](int kt) {
        const int   st = kt & (NSTAGE - 1);
        const float* Ag = AgBase + kt * BKQ;
        const float* Bg = BgBase + (size_t)kt * BKQ * Bld;
        uint32_t ad = AsW + st * (A_STG_F * 4);
        uint32_t bd = BsW + st * (B_STG_F * 4);
        #pragma unroll
        for (int r = 0; r < 4; r++) {
            cp16(ad + r * 32 * AST * 4, Ag + (size_t)(r * 32) * Kdim);
            cp16(bd + r * 8  * BST * 4, Bg + (size_t)(r * 8)  * Bld);
        }
    };

    issue(0); cpcommit();

    for (int kt = 0; kt < KT; kt++) {
        cpwait<0>();
        __syncthreads();

        if (kt + 1 < KT) issue(kt + 1);
        cpcommit();

        const int cb = kt & (NSTAGE - 1);
        const uint32_t aOff = cb * (A_STG_F * 4);
        const float* Bsc = Bs + cb * B_STG_F;

        #pragma unroll
        for (int k0 = 0; k0 < BKQ; k0 += 8) {
            uint32_t afr[4][4], bfr[4][2];
            #pragma unroll
            for (int i = 0; i < 4; i++) {
                asm volatile(
                    "ldmatrix.sync.aligned.m8n8.x4.shared.b16 {%0,%1,%2,%3}, [%4];"
                    : "=r"(afr[i][0]), "=r"(afr[i][1]),
                      "=r"(afr[i][2]), "=r"(afr[i][3])
                    : "r"(aLd[i] + aOff + k0 * 4));
            }
            #pragma unroll
            for (int j = 0; j < 4; j++) {
                int bc = wn * 32 + j * 8 + g;
                bfr[j][0] = tf32u(Bsc[(k0 + t4) * BST + bc]);
                bfr[j][1] = tf32u(Bsc[(k0 + t4 + 4) * BST + bc]);
            }
            #pragma unroll
            for (int i = 0; i < 4; i++)
                #pragma unroll
                for (int j = 0; j < 4; j++)
                    MMA_TF32(acc[i][j], afr[i][0], afr[i][1], afr[i][2], afr[i][3],
                             bfr[j][0], bfr[j][1]);
        }
        __syncthreads();
    }

    #pragma unroll
    for (int i = 0; i < 4; i++) {
        #pragma unroll
        for (int j = 0; j < 4; j++) {
            int r0 = bm0 + wm * 64 + i * 16 + g;
            int c0 = bn0 + wn * 32 + j * 8 + t4 * 2;
            #pragma unroll
            for (int half = 0; half < 2; half++) {
                int r = r0 + half * 8;
                float2 v = make_float2(acc[i][j][half * 2], acc[i][j][half * 2 + 1]);
                if (EPI == 1) {
                    float2 rr = *(const float2*)(res + (size_t)r * Cld + c0);
                    v.x = v.x + bias[c0]     + rr.x;
                    v.y = v.y + bias[c0 + 1] + rr.y;
                }
                if (EPI == 2) {
                    v.x = tf32r(gelu_tanh(v.x + bias[c0]));
                    v.y = tf32r(gelu_tanh(v.y + bias[c0 + 1]));
                }
                *(float2*)(C + (size_t)r * Cld + c0) = v;
            }
        }
    }
}

// ---------------- mma-based fused causal flash attention ----------------
// Block: 64 q-rows of one (b,h); 4 warps x 16 q-rows. tf32 mma for S=QK^T and PV.
// Tiles are 64 floats wide. Strides: QST/KST/PST=68 (68/4 odd -> ldmatrix
// conflict-free; B-frag bank = 4g+t4+const permutation), VST=72 (bank = 8t4+g).
#define QST 68
#define KST 68
#define VST 72
#define PST 68
#define ATTN_SMEM ((64*QST + 64*KST + 64*VST + 4*16*PST + 64) * 4)   // 70912 B

__global__ void __launch_bounds__(128) attn_kernel(
    const float* __restrict__ qkv, const int* __restrict__ mask,
    float* __restrict__ ctx)
{
    extern __shared__ float asm_[];
    float* Qs = asm_;                    // 64*QST
    float* Ks = Qs + 64 * QST;           // 64*KST
    float* Vs = Ks + 64 * KST;           // 64*VST
    float* Pb = Vs + 64 * VST;           // 4 * 16*PST
    float* Ms = Pb + 4 * 16 * PST;       // 64

    const int b = blockIdx.z, h = blockIdx.y, qt = blockIdx.x;
    const int q0 = qt * 64;
    const int t = threadIdx.x;
    const int w = t >> 5, lane = t & 31;
    const int g = lane >> 2, t4 = lane & 3;
    float* Pw = Pb + w * 16 * PST;

    // ---- stage Q (scaled by 1/8, tf32-rounded) ----
    {
        int row = t >> 1, ch = (t & 1) * 8;     // 8 float4 per thread
        const float4* src = (const float4*)(qkv + (size_t)(b * SS + q0 + row) * 3 * DDIM
                                            + h * HDIM) + ch;
        float* dst = Qs + row * QST + ch * 4;
        #pragma unroll
        for (int i = 0; i < 8; i++) {
            float4 v = src[i];
            dst[i*4+0] = tf32r(v.x * 0.125f);
            dst[i*4+1] = tf32r(v.y * 0.125f);
            dst[i*4+2] = tf32r(v.z * 0.125f);
            dst[i*4+3] = tf32r(v.w * 0.125f);
        }
    }

    // ldmatrix lane pointers
    const int lrow = lane & 15, lcol = (lane >> 4) * 4;
    const uint32_t qLd = (uint32_t)__cvta_generic_to_shared(
        &Qs[(w * 16 + lrow) * QST + lcol]);
    const uint32_t pLd = (uint32_t)__cvta_generic_to_shared(
        &Pw[lrow * PST + lcol]);

    float O[8][4];
    #pragma unroll
    for (int j = 0; j < 8; j++)
        #pragma unroll
        for (int c = 0; c < 4; c++) O[j][c] = 0.f;
    float m0 = -1e30f, m1 = -1e30f, l0 = 0.f, l1 = 0.f;
    const int qg0 = q0 + w * 16 + g, qg1 = qg0 + 8;

    for (int kt = 0; kt <= qt; kt++) {
        __syncthreads();
        // ---- stage K (tf32), V (tf32), pad-mask ----
        {
            int row = t >> 1, ch = (t & 1) * 8;
            size_t base = (size_t)(b * SS + kt * 64 + row) * 3 * DDIM + h * HDIM;
            const float4* ks = (const float4*)(qkv + base + DDIM) + ch;
            const float4* vs = (const float4*)(qkv + base + 2 * DDIM) + ch;
            float* kd = Ks + row * KST + ch * 4;
            float* vd = Vs + row * VST + ch * 4;
            #pragma unroll
            for (int i = 0; i < 8; i++) {
                float4 kv = ks[i];
                kd[i*4+0] = tf32r(kv.x); kd[i*4+1] = tf32r(kv.y);
                kd[i*4+2] = tf32r(kv.z); kd[i*4+3] = tf32r(kv.w);
                float4 vv = vs[i];
                vd[i*4+0] = tf32r(vv.x); vd[i*4+1] = tf32r(vv.y);
                vd[i*4+2] = tf32r(vv.z); vd[i*4+3] = tf32r(vv.w);
            }
            if (t < 64)
                Ms[t] = mask[b * SS + kt * 64 + t] ? 0.f : -1e30f;
        }
        __syncthreads();

        // ---- S = Q @ K^T : 8 n-tiles x 8 k-steps ----
        float s[8][4];
        #pragma unroll
        for (int j = 0; j < 8; j++)
            #pragma unroll
            for (int c = 0; c < 4; c++) s[j][c] = 0.f;

        #pragma unroll
        for (int k0 = 0; k0 < 64; k0 += 8) {
            uint32_t a0, a1, a2, a3;
            asm volatile(
                "ldmatrix.sync.aligned.m8n8.x4.shared.b16 {%0,%1,%2,%3}, [%4];"
                : "=r"(a0), "=r"(a1), "=r"(a2), "=r"(a3)
                : "r"(qLd + k0 * 4));
            #pragma unroll
            for (int j = 0; j < 8; j++) {
                uint32_t b0 = __float_as_uint(Ks[(j * 8 + g) * KST + k0 + t4]);
                uint32_t b1 = __float_as_uint(Ks[(j * 8 + g) * KST + k0 + t4 + 4]);
                MMA_TF32(s[j], a0, a1, a2, a3, b0, b1);
            }
        }

        // ---- mask + online softmax on fragments ----
        const bool diag = (kt == qt);
        float mt0 = -1e30f, mt1 = -1e30f;
        #pragma unroll
        for (int j = 0; j < 8; j++) {
            int n0 = j * 8 + 2 * t4;
            float pm0 = Ms[n0], pm1 = Ms[n0 + 1];
            float v0 = s[j][0] + pm0, v1 = s[j][1] + pm1;
            float v2 = s[j][2] + pm0, v3 = s[j][3] + pm1;
            if (diag) {
                int kg = kt * 64 + n0;
                if (kg     > qg0) v0 = -1e30f;
                if (kg + 1 > qg0) v1 = -1e30f;
                if (kg     > qg1) v2 = -1e30f;
                if (kg + 1 > qg1) v3 = -1e30f;
            }
            s[j][0] = v0; s[j][1] = v1; s[j][2] = v2; s[j][3] = v3;
            mt0 = fmaxf(mt0, fmaxf(v0, v1));
            mt1 = fmaxf(mt1, fmaxf(v2, v3));
        }
        mt0 = fmaxf(mt0, __shfl_xor_sync(0xffffffffu, mt0, 1));
        mt0 = fmaxf(mt0, __shfl_xor_sync(0xffffffffu, mt0, 2));
        mt1 = fmaxf(mt1, __shfl_xor_sync(0xffffffffu, mt1, 1));
        mt1 = fmaxf(mt1, __shfl_xor_sync(0xffffffffu, mt1, 2));

        float mn0 = fmaxf(m0, mt0), mn1 = fmaxf(m1, mt1);
        float corr0 = __expf(m0 - mn0), corr1 = __expf(m1 - mn1);
        m0 = mn0; m1 = mn1;

        float ls0 = 0.f, ls1 = 0.f;
        #pragma unroll
        for (int j = 0; j < 8; j++) {
            float p0 = __expf(s[j][0] - mn0);
            float p1 = __expf(s[j][1] - mn0);
            float p2 = __expf(s[j][2] - mn1);
            float p3 = __expf(s[j][3] - mn1);
            ls0 += p0 + p1; ls1 += p2 + p3;
            int n0 = j * 8 + 2 * t4;
            *(float2*)&Pw[g * PST + n0]       = make_float2(tf32r(p0), tf32r(p1));
            *(float2*)&Pw[(g + 8) * PST + n0] = make_float2(tf32r(p2), tf32r(p3));
        }
        ls0 += __shfl_xor_sync(0xffffffffu, ls0, 1);
        ls0 += __shfl_xor_sync(0xffffffffu, ls0, 2);
        ls1 += __shfl_xor_sync(0xffffffffu, ls1, 1);
        ls1 += __shfl_xor_sync(0xffffffffu, ls1, 2);
        l0 = l0 * corr0 + ls0;
        l1 = l1 * corr1 + ls1;

        #pragma unroll
        for (int j = 0; j < 8; j++) {
            O[j][0] *= corr0; O[j][1] *= corr0;
            O[j][2] *= corr1; O[j][3] *= corr1;
        }
        __syncwarp();

        // ---- O += P @ V : 8 k-chunks ----
        #pragma unroll
        for (int kc = 0; kc < 8; kc++) {
            uint32_t a0, a1, a2, a3;
            asm volatile(
                "ldmatrix.sync.aligned.m8n8.x4.shared.b16 {%0,%1,%2,%3}, [%4];"
                : "=r"(a0), "=r"(a1), "=r"(a2), "=r"(a3)
                : "r"(pLd + kc * 32));
            #pragma unroll
            for (int j = 0; j < 8; j++) {
                uint32_t b0 = __float_as_uint(Vs[(kc * 8 + t4) * VST + j * 8 + g]);
                uint32_t b1 = __float_as_uint(Vs[(kc * 8 + t4 + 4) * VST + j * 8 + g]);
                MMA_TF32(O[j], a0, a1, a2, a3, b0, b1);
            }
        }
        __syncwarp();
    }

    // ---- final normalize + store (tf32-rounded for the Wo gemm) ----
    float inv0 = 1.f / l0, inv1 = 1.f / l1;
    float* o0 = ctx + (size_t)(b * SS + qg0) * DDIM + h * HDIM;
    float* o1 = ctx + (size_t)(b * SS + qg1) * DDIM + h * HDIM;
    #pragma unroll
    for (int j = 0; j < 8; j++) {
        int n0 = j * 8 + 2 * t4;
        *(float2*)(o0 + n0) = make_float2(tf32r(O[j][0] * inv0), tf32r(O[j][1] * inv0));
        *(float2*)(o1 + n0) = make_float2(tf32r(O[j][2] * inv1), tf32r(O[j][3] * inv1));
    }
}

// ---------------- launch ----------------
extern "C" void kernel_launch(void* const* d_in, const int* in_sizes, int n_in,
                              void* d_out, int out_size) {
    const float* x     = (const float*)d_in[0];
    const int*   amask = (const int*)  d_in[1];
    const float* wq    = (const float*)d_in[2];
    const float* wk    = (const float*)d_in[3];
    const float* wv    = (const float*)d_in[4];
    const float* wo    = (const float*)d_in[5];
    const float* bo    = (const float*)d_in[6];
    const float* ln1s  = (const float*)d_in[7];
    const float* ln1b  = (const float*)d_in[8];
    const float* ln2s  = (const float*)d_in[9];
    const float* ln2b  = (const float*)d_in[10];
    const float* w1    = (const float*)d_in[11];
    const float* b1    = (const float*)d_in[12];
    const float* w2    = (const float*)d_in[13];
    const float* b2    = (const float*)d_in[14];
    float* out = (float*)d_out;

    float *h, *qkv, *ctx, *x2, *mid;
    cudaGetSymbolAddress((void**)&h,   g_h);
    cudaGetSymbolAddress((void**)&qkv, g_qkv);
    cudaGetSymbolAddress((void**)&ctx, g_ctx);
    cudaGetSymbolAddress((void**)&x2,  g_x2);
    cudaGetSymbolAddress((void**)&mid, g_mid);

    cudaFuncSetAttribute(gemm_kernel<0>, cudaFuncAttributeMaxDynamicSharedMemorySize, GEMM_SMEM);
    cudaFuncSetAttribute(gemm_kernel<1>, cudaFuncAttributeMaxDynamicSharedMemorySize, GEMM_SMEM);
    cudaFuncSetAttribute(gemm_kernel<2>, cudaFuncAttributeMaxDynamicSharedMemorySize, GEMM_SMEM);
    cudaFuncSetAttribute(attn_kernel,    cudaFuncAttributeMaxDynamicSharedMemorySize, ATTN_SMEM);

    // --- attention half ---
    ln_kernel<<<MTOT, 256>>>(x, ln1s, ln1b, h);
    gemm_kernel<0><<<dim3(DDIM/BN, MTOT/BM), 256, GEMM_SMEM>>>(
        h, wq, nullptr, nullptr, qkv + 0,        DDIM, DDIM, 3*DDIM);
    gemm_kernel<0><<<dim3(DDIM/BN, MTOT/BM), 256, GEMM_SMEM>>>(
        h, wk, nullptr, nullptr, qkv + DDIM,     DDIM, DDIM, 3*DDIM);
    gemm_kernel<0><<<dim3(DDIM/BN, MTOT/BM), 256, GEMM_SMEM>>>(
        h, wv, nullptr, nullptr, qkv + 2*DDIM,   DDIM, DDIM, 3*DDIM);
    attn_kernel<<<dim3(SS/64, HH, BB), 128, ATTN_SMEM>>>(qkv, amask, ctx);
    gemm_kernel<1><<<dim3(DDIM/BN, MTOT/BM), 256, GEMM_SMEM>>>(
        ctx, wo, bo, x, x2, DDIM, DDIM, DDIM);

    // --- FFN half ---
    ln_kernel<<<MTOT, 256>>>(x2, ln2s, ln2b, h);
    gemm_kernel<2><<<dim3(DFF/BN, MTOT/BM), 256, GEMM_SMEM>>>(
        h, w1, b1, nullptr, mid, DDIM, DFF, DFF);
    gemm_kernel<1><<<dim3(DDIM/BN, MTOT/BM), 256, GEMM_SMEM>>>(
        mid, w2, b2, x2, out, DFF, DDIM, DDIM);
}

// round 9
// speedup vs baseline: 2.8415x; 1.0002x over previous
#include <cuda_runtime.h>
#include <cstdint>

// ---------------- problem dims ----------------
#define BB 4
#define SS 1024
#define DDIM 1024
#define HH 16
#define HDIM 64
#define DFF 4096
#define MTOT (BB*SS)   // 4096

// ---------------- device scratch (no allocs allowed) ----------------
__device__ float g_h   [MTOT*DDIM];
__device__ float g_qkv [(size_t)MTOT*3*DDIM];
__device__ float g_ctx [MTOT*DDIM];
__device__ float g_x2  [MTOT*DDIM];
__device__ float g_mid [(size_t)MTOT*DFF];
// tf32-pre-rounded weights (same layout as inputs)
__device__ float g_rwq [DDIM*DDIM];
__device__ float g_rwk [DDIM*DDIM];
__device__ float g_rwv [DDIM*DDIM];
__device__ float g_rwo [DDIM*DDIM];
__device__ float g_rw1 [(size_t)DDIM*DFF];
__device__ float g_rw2 [(size_t)DFF*DDIM];

// ---------------- helpers ----------------
__device__ __forceinline__ float tf32r(float x) {
    uint32_t u;
    asm("cvt.rna.tf32.f32 %0, %1;" : "=r"(u) : "f"(x));
    return __uint_as_float(u);
}
__device__ __forceinline__ void cp16(uint32_t dst, const void* src) {
    asm volatile("cp.async.cg.shared.global [%0], [%1], 16;" :: "r"(dst), "l"(src));
}
__device__ __forceinline__ void cpcommit() { asm volatile("cp.async.commit_group;"); }
template<int N> __device__ __forceinline__ void cpwait() {
    asm volatile("cp.async.wait_group %0;" :: "n"(N));
}
__device__ __forceinline__ float gelu_tanh(float v) {
    const float c = 0.79788456080286535588f;  // sqrt(2/pi)
    float u = c * (v + 0.044715f * v * v * v);
    return 0.5f * v * (1.f + tanhf(u));
}

#define MMA_TF32(acc, a0,a1,a2,a3, b0,b1) \
    asm volatile( \
        "mma.sync.aligned.m16n8k8.row.col.f32.tf32.tf32.f32 " \
        "{%0,%1,%2,%3},{%4,%5,%6,%7},{%8,%9},{%0,%1,%2,%3};\n" \
        : "+f"((acc)[0]), "+f"((acc)[1]), "+f"((acc)[2]), "+f"((acc)[3]) \
        : "r"(a0), "r"(a1), "r"(a2), "r"(a3), "r"(b0), "r"(b1))

// ---------------- weight prep: tf32 rounding (vectorized) ----------------
__global__ void round_copy4(const float4* __restrict__ src, float4* __restrict__ dst) {
    int i = blockIdx.x * 256 + threadIdx.x;
    float4 v = src[i];
    v.x = tf32r(v.x); v.y = tf32r(v.y); v.z = tf32r(v.z); v.w = tf32r(v.w);
    dst[i] = v;
}

// ---------------- LayerNorm (row = 1024), output rounded to tf32 ----------------
__global__ void ln_kernel(const float* __restrict__ x,
                          const float* __restrict__ scale,
                          const float* __restrict__ shift,
                          float* __restrict__ out) {
    int row = blockIdx.x;
    int t = threadIdx.x;                 // 256 threads, 4 floats each
    const float4* xr = (const float4*)(x + (size_t)row * DDIM);
    float4 v = xr[t];
    float s  = v.x + v.y + v.z + v.w;
    float s2 = v.x*v.x + v.y*v.y + v.z*v.z + v.w*v.w;
    #pragma unroll
    for (int o = 16; o >= 1; o >>= 1) {
        s  += __shfl_xor_sync(0xffffffffu, s,  o);
        s2 += __shfl_xor_sync(0xffffffffu, s2, o);
    }
    __shared__ float red[2][8];
    __shared__ float bcast[2];
    int wid = t >> 5, lane = t & 31;
    if (lane == 0) { red[0][wid] = s; red[1][wid] = s2; }
    __syncthreads();
    if (t == 0) {
        float S = 0.f, S2 = 0.f;
        #pragma unroll
        for (int i = 0; i < 8; i++) { S += red[0][i]; S2 += red[1][i]; }
        float m = S * (1.f / DDIM);
        float var = S2 * (1.f / DDIM) - m * m;
        bcast[0] = m;
        bcast[1] = rsqrtf(var + 1e-5f);
    }
    __syncthreads();
    float m = bcast[0], inv = bcast[1];
    float4 sc = ((const float4*)scale)[t];
    float4 sh = ((const float4*)shift)[t];
    float4 o;
    o.x = tf32r(sc.x * (v.x - m) * inv + sh.x);
    o.y = tf32r(sc.y * (v.y - m) * inv + sh.y);
    o.z = tf32r(sc.z * (v.z - m) * inv + sh.z);
    o.w = tf32r(sc.w * (v.w - m) * inv + sh.w);
    ((float4*)(out + (size_t)row * DDIM))[t] = o;
}

// ---------------- TF32 mma GEMM: C[M,N] = A[M,K] @ W[K,N] (+epilogue) ----------------
// A and W are both pre-rounded tf32.  3-stage cp.async ring, ONE sync per k-iter.
// EPI: 0 plain fp32 store, 1 +bias[n]+res[m,n], 2 tf32r(gelu(acc+bias))
#define BM 128
#define BN 128
#define BKQ 32
#define AST 36
#define BST 136
#define NSTAGE 3

#define A_STG_F (BM * AST)
#define B_STG_F (BKQ * BST)
#define GEMM_SMEM ((NSTAGE * (A_STG_F + B_STG_F)) * 4)   // 107520 B

template<int EPI>
__global__ void __launch_bounds__(256, 2) gemm_kernel(
    const float* __restrict__ A, const float* __restrict__ Wt,
    const float* __restrict__ bias, const float* __restrict__ res,
    float* __restrict__ C, int Kdim, int Bld, int Cld)
{
    extern __shared__ float smem[];
    float* As = smem;
    float* Bs = smem + NSTAGE * A_STG_F;

    const int tid  = threadIdx.x;
    const int bm0  = blockIdx.y * BM;
    const int bn0  = blockIdx.x * BN;
    const int wid  = tid >> 5, lane = tid & 31;
    const int wm   = wid >> 2;
    const int wn   = wid & 3;
    const int g    = lane >> 2;
    const int t4   = lane & 3;

    float acc[4][4][4];
    #pragma unroll
    for (int i = 0; i < 4; i++)
        #pragma unroll
        for (int j = 0; j < 4; j++)
            #pragma unroll
            for (int c = 0; c < 4; c++) acc[i][j][c] = 0.f;

    const int arow = tid >> 3, ac8 = tid & 7;
    const int brow = tid >> 5, bc4 = tid & 31;
    const float* AgBase = A  + (size_t)(bm0 + arow) * Kdim + ac8 * 4;
    const float* BgBase = Wt + (size_t)brow * Bld + bn0 + bc4 * 4;
    const uint32_t AsW = (uint32_t)__cvta_generic_to_shared(&As[arow * AST + ac8 * 4]);
    const uint32_t BsW = (uint32_t)__cvta_generic_to_shared(&Bs[brow * BST + bc4 * 4]);

    const int lrow = lane & 15;
    const int lcol = (lane >> 4) * 4;
    uint32_t aLd[4];
    #pragma unroll
    for (int i = 0; i < 4; i++)
        aLd[i] = (uint32_t)__cvta_generic_to_shared(
            &As[(wm * 64 + i * 16 + lrow) * AST + lcol]);

    const int KT = Kdim / BKQ;

    auto issue = [&](int kt) {
        const int   st = kt % NSTAGE;
        const float* Ag = AgBase + kt * BKQ;
        const float* Bg = BgBase + (size_t)kt * BKQ * Bld;
        uint32_t ad = AsW + st * (A_STG_F * 4);
        uint32_t bd = BsW + st * (B_STG_F * 4);
        #pragma unroll
        for (int r = 0; r < 4; r++) {
            cp16(ad + r * 32 * AST * 4, Ag + (size_t)(r * 32) * Kdim);
            cp16(bd + r * 8  * BST * 4, Bg + (size_t)(r * 8)  * Bld);
        }
    };

    issue(0); cpcommit();
    issue(1); cpcommit();

    for (int kt = 0; kt < KT; kt++) {
        cpwait<1>();              // group kt complete (FIFO)
        __syncthreads();          // all warps done with compute(kt-1), data visible

        if (kt + 2 < KT) issue(kt + 2);   // writes stage (kt-1)%3 — safe after sync
        cpcommit();

        const int cb = kt % NSTAGE;
        const uint32_t aOff = cb * (A_STG_F * 4);
        const float* Bsc = Bs + cb * B_STG_F;

        #pragma unroll
        for (int k0 = 0; k0 < BKQ; k0 += 8) {
            uint32_t afr[4][4], bfr[4][2];
            #pragma unroll
            for (int i = 0; i < 4; i++) {
                asm volatile(
                    "ldmatrix.sync.aligned.m8n8.x4.shared.b16 {%0,%1,%2,%3}, [%4];"
                    : "=r"(afr[i][0]), "=r"(afr[i][1]),
                      "=r"(afr[i][2]), "=r"(afr[i][3])
                    : "r"(aLd[i] + aOff + k0 * 4));
            }
            #pragma unroll
            for (int j = 0; j < 4; j++) {
                int bc = wn * 32 + j * 8 + g;
                bfr[j][0] = __float_as_uint(Bsc[(k0 + t4) * BST + bc]);
                bfr[j][1] = __float_as_uint(Bsc[(k0 + t4 + 4) * BST + bc]);
            }
            #pragma unroll
            for (int i = 0; i < 4; i++)
                #pragma unroll
                for (int j = 0; j < 4; j++)
                    MMA_TF32(acc[i][j], afr[i][0], afr[i][1], afr[i][2], afr[i][3],
                             bfr[j][0], bfr[j][1]);
        }
    }

    #pragma unroll
    for (int i = 0; i < 4; i++) {
        #pragma unroll
        for (int j = 0; j < 4; j++) {
            int r0 = bm0 + wm * 64 + i * 16 + g;
            int c0 = bn0 + wn * 32 + j * 8 + t4 * 2;
            #pragma unroll
            for (int half = 0; half < 2; half++) {
                int r = r0 + half * 8;
                float2 v = make_float2(acc[i][j][half * 2], acc[i][j][half * 2 + 1]);
                if (EPI == 1) {
                    float2 rr = *(const float2*)(res + (size_t)r * Cld + c0);
                    v.x = v.x + bias[c0]     + rr.x;
                    v.y = v.y + bias[c0 + 1] + rr.y;
                }
                if (EPI == 2) {
                    v.x = tf32r(gelu_tanh(v.x + bias[c0]));
                    v.y = tf32r(gelu_tanh(v.y + bias[c0 + 1]));
                }
                *(float2*)(C + (size_t)r * Cld + c0) = v;
            }
        }
    }
}

// ---------------- mma-based fused causal flash attention (proven R7) ----------------
#define QST 68
#define KST 68
#define VST 72
#define PST 68
#define ATTN_SMEM ((64*QST + 64*KST + 64*VST + 4*16*PST + 64) * 4)   // 70912 B

__global__ void __launch_bounds__(128) attn_kernel(
    const float* __restrict__ qkv, const int* __restrict__ mask,
    float* __restrict__ ctx)
{
    extern __shared__ float asm_[];
    float* Qs = asm_;
    float* Ks = Qs + 64 * QST;
    float* Vs = Ks + 64 * KST;
    float* Pb = Vs + 64 * VST;
    float* Ms = Pb + 4 * 16 * PST;

    const int b = blockIdx.z, h = blockIdx.y, qt = blockIdx.x;
    const int q0 = qt * 64;
    const int t = threadIdx.x;
    const int w = t >> 5, lane = t & 31;
    const int g = lane >> 2, t4 = lane & 3;
    float* Pw = Pb + w * 16 * PST;

    {
        int row = t >> 1, ch = (t & 1) * 8;
        const float4* src = (const float4*)(qkv + (size_t)(b * SS + q0 + row) * 3 * DDIM
                                            + h * HDIM) + ch;
        float* dst = Qs + row * QST + ch * 4;
        #pragma unroll
        for (int i = 0; i < 8; i++) {
            float4 v = src[i];
            dst[i*4+0] = tf32r(v.x * 0.125f);
            dst[i*4+1] = tf32r(v.y * 0.125f);
            dst[i*4+2] = tf32r(v.z * 0.125f);
            dst[i*4+3] = tf32r(v.w * 0.125f);
        }
    }

    const int lrow = lane & 15, lcol = (lane >> 4) * 4;
    const uint32_t qLd = (uint32_t)__cvta_generic_to_shared(
        &Qs[(w * 16 + lrow) * QST + lcol]);
    const uint32_t pLd = (uint32_t)__cvta_generic_to_shared(
        &Pw[lrow * PST + lcol]);

    float O[8][4];
    #pragma unroll
    for (int j = 0; j < 8; j++)
        #pragma unroll
        for (int c = 0; c < 4; c++) O[j][c] = 0.f;
    float m0 = -1e30f, m1 = -1e30f, l0 = 0.f, l1 = 0.f;
    const int qg0 = q0 + w * 16 + g, qg1 = qg0 + 8;

    for (int kt = 0; kt <= qt; kt++) {
        __syncthreads();
        {
            int row = t >> 1, ch = (t & 1) * 8;
            size_t base = (size_t)(b * SS + kt * 64 + row) * 3 * DDIM + h * HDIM;
            const float4* ks = (const float4*)(qkv + base + DDIM) + ch;
            const float4* vs = (const float4*)(qkv + base + 2 * DDIM) + ch;
            float* kd = Ks + row * KST + ch * 4;
            float* vd = Vs + row * VST + ch * 4;
            #pragma unroll
            for (int i = 0; i < 8; i++) {
                float4 kv = ks[i];
                kd[i*4+0] = tf32r(kv.x); kd[i*4+1] = tf32r(kv.y);
                kd[i*4+2] = tf32r(kv.z); kd[i*4+3] = tf32r(kv.w);
                float4 vv = vs[i];
                vd[i*4+0] = tf32r(vv.x); vd[i*4+1] = tf32r(vv.y);
                vd[i*4+2] = tf32r(vv.z); vd[i*4+3] = tf32r(vv.w);
            }
            if (t < 64)
                Ms[t] = mask[b * SS + kt * 64 + t] ? 0.f : -1e30f;
        }
        __syncthreads();

        float s[8][4];
        #pragma unroll
        for (int j = 0; j < 8; j++)
            #pragma unroll
            for (int c = 0; c < 4; c++) s[j][c] = 0.f;

        #pragma unroll
        for (int k0 = 0; k0 < 64; k0 += 8) {
            uint32_t a0, a1, a2, a3;
            asm volatile(
                "ldmatrix.sync.aligned.m8n8.x4.shared.b16 {%0,%1,%2,%3}, [%4];"
                : "=r"(a0), "=r"(a1), "=r"(a2), "=r"(a3)
                : "r"(qLd + k0 * 4));
            #pragma unroll
            for (int j = 0; j < 8; j++) {
                uint32_t b0 = __float_as_uint(Ks[(j * 8 + g) * KST + k0 + t4]);
                uint32_t b1 = __float_as_uint(Ks[(j * 8 + g) * KST + k0 + t4 + 4]);
                MMA_TF32(s[j], a0, a1, a2, a3, b0, b1);
            }
        }

        const bool diag = (kt == qt);
        float mt0 = -1e30f, mt1 = -1e30f;
        #pragma unroll
        for (int j = 0; j < 8; j++) {
            int n0 = j * 8 + 2 * t4;
            float pm0 = Ms[n0], pm1 = Ms[n0 + 1];
            float v0 = s[j][0] + pm0, v1 = s[j][1] + pm1;
            float v2 = s[j][2] + pm0, v3 = s[j][3] + pm1;
            if (diag) {
                int kg = kt * 64 + n0;
                if (kg     > qg0) v0 = -1e30f;
                if (kg + 1 > qg0) v1 = -1e30f;
                if (kg     > qg1) v2 = -1e30f;
                if (kg + 1 > qg1) v3 = -1e30f;
            }
            s[j][0] = v0; s[j][1] = v1; s[j][2] = v2; s[j][3] = v3;
            mt0 = fmaxf(mt0, fmaxf(v0, v1));
            mt1 = fmaxf(mt1, fmaxf(v2, v3));
        }
        mt0 = fmaxf(mt0, __shfl_xor_sync(0xffffffffu, mt0, 1));
        mt0 = fmaxf(mt0, __shfl_xor_sync(0xffffffffu, mt0, 2));
        mt1 = fmaxf(mt1, __shfl_xor_sync(0xffffffffu, mt1, 1));
        mt1 = fmaxf(mt1, __shfl_xor_sync(0xffffffffu, mt1, 2));

        float mn0 = fmaxf(m0, mt0), mn1 = fmaxf(m1, mt1);
        float corr0 = __expf(m0 - mn0), corr1 = __expf(m1 - mn1);
        m0 = mn0; m1 = mn1;

        float ls0 = 0.f, ls1 = 0.f;
        #pragma unroll
        for (int j = 0; j < 8; j++) {
            float p0 = __expf(s[j][0] - mn0);
            float p1 = __expf(s[j][1] - mn0);
            float p2 = __expf(s[j][2] - mn1);
            float p3 = __expf(s[j][3] - mn1);
            ls0 += p0 + p1; ls1 += p2 + p3;
            int n0 = j * 8 + 2 * t4;
            *(float2*)&Pw[g * PST + n0]       = make_float2(tf32r(p0), tf32r(p1));
            *(float2*)&Pw[(g + 8) * PST + n0] = make_float2(tf32r(p2), tf32r(p3));
        }
        ls0 += __shfl_xor_sync(0xffffffffu, ls0, 1);
        ls0 += __shfl_xor_sync(0xffffffffu, ls0, 2);
        ls1 += __shfl_xor_sync(0xffffffffu, ls1, 1);
        ls1 += __shfl_xor_sync(0xffffffffu, ls1, 2);
        l0 = l0 * corr0 + ls0;
        l1 = l1 * corr1 + ls1;

        #pragma unroll
        for (int j = 0; j < 8; j++) {
            O[j][0] *= corr0; O[j][1] *= corr0;
            O[j][2] *= corr1; O[j][3] *= corr1;
        }
        __syncwarp();

        #pragma unroll
        for (int kc = 0; kc < 8; kc++) {
            uint32_t a0, a1, a2, a3;
            asm volatile(
                "ldmatrix.sync.aligned.m8n8.x4.shared.b16 {%0,%1,%2,%3}, [%4];"
                : "=r"(a0), "=r"(a1), "=r"(a2), "=r"(a3)
                : "r"(pLd + kc * 32));
            #pragma unroll
            for (int j = 0; j < 8; j++) {
                uint32_t b0 = __float_as_uint(Vs[(kc * 8 + t4) * VST + j * 8 + g]);
                uint32_t b1 = __float_as_uint(Vs[(kc * 8 + t4 + 4) * VST + j * 8 + g]);
                MMA_TF32(O[j], a0, a1, a2, a3, b0, b1);
            }
        }
        __syncwarp();
    }

    float inv0 = 1.f / l0, inv1 = 1.f / l1;
    float* o0 = ctx + (size_t)(b * SS + qg0) * DDIM + h * HDIM;
    float* o1 = ctx + (size_t)(b * SS + qg1) * DDIM + h * HDIM;
    #pragma unroll
    for (int j = 0; j < 8; j++) {
        int n0 = j * 8 + 2 * t4;
        *(float2*)(o0 + n0) = make_float2(tf32r(O[j][0] * inv0), tf32r(O[j][1] * inv0));
        *(float2*)(o1 + n0) = make_float2(tf32r(O[j][2] * inv1), tf32r(O[j][3] * inv1));
    }
}

// ---------------- launch ----------------
extern "C" void kernel_launch(void* const* d_in, const int* in_sizes, int n_in,
                              void* d_out, int out_size) {
    const float* x     = (const float*)d_in[0];
    const int*   amask = (const int*)  d_in[1];
    const float* wq    = (const float*)d_in[2];
    const float* wk    = (const float*)d_in[3];
    const float* wv    = (const float*)d_in[4];
    const float* wo    = (const float*)d_in[5];
    const float* bo    = (const float*)d_in[6];
    const float* ln1s  = (const float*)d_in[7];
    const float* ln1b  = (const float*)d_in[8];
    const float* ln2s  = (const float*)d_in[9];
    const float* ln2b  = (const float*)d_in[10];
    const float* w1    = (const float*)d_in[11];
    const float* b1    = (const float*)d_in[12];
    const float* w2    = (const float*)d_in[13];
    const float* b2    = (const float*)d_in[14];
    float* out = (float*)d_out;

    float *h, *qkv, *ctx, *x2, *mid, *rwq, *rwk, *rwv, *rwo, *rw1, *rw2;
    cudaGetSymbolAddress((void**)&h,   g_h);
    cudaGetSymbolAddress((void**)&qkv, g_qkv);
    cudaGetSymbolAddress((void**)&ctx, g_ctx);
    cudaGetSymbolAddress((void**)&x2,  g_x2);
    cudaGetSymbolAddress((void**)&mid, g_mid);
    cudaGetSymbolAddress((void**)&rwq, g_rwq);
    cudaGetSymbolAddress((void**)&rwk, g_rwk);
    cudaGetSymbolAddress((void**)&rwv, g_rwv);
    cudaGetSymbolAddress((void**)&rwo, g_rwo);
    cudaGetSymbolAddress((void**)&rw1, g_rw1);
    cudaGetSymbolAddress((void**)&rw2, g_rw2);

    cudaFuncSetAttribute(gemm_kernel<0>, cudaFuncAttributeMaxDynamicSharedMemorySize, GEMM_SMEM);
    cudaFuncSetAttribute(gemm_kernel<1>, cudaFuncAttributeMaxDynamicSharedMemorySize, GEMM_SMEM);
    cudaFuncSetAttribute(gemm_kernel<2>, cudaFuncAttributeMaxDynamicSharedMemorySize, GEMM_SMEM);
    cudaFuncSetAttribute(attn_kernel,    cudaFuncAttributeMaxDynamicSharedMemorySize, ATTN_SMEM);

    // weight prep: tf32 rounding once per launch
    round_copy4<<<DDIM*DDIM/1024, 256>>>((const float4*)wq, (float4*)rwq);
    round_copy4<<<DDIM*DDIM/1024, 256>>>((const float4*)wk, (float4*)rwk);
    round_copy4<<<DDIM*DDIM/1024, 256>>>((const float4*)wv, (float4*)rwv);
    round_copy4<<<DDIM*DDIM/1024, 256>>>((const float4*)wo, (float4*)rwo);
    round_copy4<<<DDIM*DFF /1024, 256>>>((const float4*)w1, (float4*)rw1);
    round_copy4<<<DFF*DDIM /1024, 256>>>((const float4*)w2, (float4*)rw2);

    // --- attention half ---
    ln_kernel<<<MTOT, 256>>>(x, ln1s, ln1b, h);
    gemm_kernel<0><<<dim3(DDIM/BN, MTOT/BM), 256, GEMM_SMEM>>>(
        h, rwq, nullptr, nullptr, qkv + 0,        DDIM, DDIM, 3*DDIM);
    gemm_kernel<0><<<dim3(DDIM/BN, MTOT/BM), 256, GEMM_SMEM>>>(
        h, rwk, nullptr, nullptr, qkv + DDIM,     DDIM, DDIM, 3*DDIM);
    gemm_kernel<0><<<dim3(DDIM/BN, MTOT/BM), 256, GEMM_SMEM>>>(
        h, rwv, nullptr, nullptr, qkv + 2*DDIM,   DDIM, DDIM, 3*DDIM);
    attn_kernel<<<dim3(SS/64, HH, BB), 128, ATTN_SMEM>>>(qkv, amask, ctx);
    gemm_kernel<1><<<dim3(DDIM/BN, MTOT/BM), 256, GEMM_SMEM>>>(
        ctx, rwo, bo, x, x2, DDIM, DDIM, DDIM);

    // --- FFN half ---
    ln_kernel<<<MTOT, 256>>>(x2, ln2s, ln2b, h);
    gemm_kernel<2><<<dim3(DFF/BN, MTOT/BM), 256, GEMM_SMEM>>>(
        h, rw1, b1, nullptr, mid, DDIM, DFF, DFF);
    gemm_kernel<1><<<dim3(DDIM/BN, MTOT/BM), 256, GEMM_SMEM>>>(
        mid, rw2, b2, x2, out, DFF, DDIM, DDIM);
}